// round 1
// baseline (speedup 1.0000x reference)
#include <cuda_runtime.h>
#include <math.h>

#define NB 4
#define NT 2048
#define NC 1024
#define NH 16
#define HD 64
#define MM (NB*NT)          // 8192 rows

// Scratch (device globals: allowed; no runtime allocation)
__device__ float g_q[(size_t)NB*NH*NT*HD];   // [b][h][t][d]
__device__ float g_k[(size_t)NB*NH*NT*HD];
__device__ float g_v[(size_t)NB*NH*NT*HD];
__device__ float g_att[(size_t)MM*NC];       // [b*t][h*64+d]

// ---------------------------------------------------------------------------
// GEMM: C[m][n] = sum_k A[m][k] * W[n][k]   (A row-major MxK, W row-major NxK)
// BM=BN=128, BK=16, 256 threads, 8x8 per-thread tile.
// ---------------------------------------------------------------------------

__global__ __launch_bounds__(256) void qkv_gemm_kernel(
    const float* __restrict__ A, const float* __restrict__ W)
{
    __shared__ float As[16][128];
    __shared__ float Bs[16][128];
    const int tid = threadIdx.x;
    const int tx = tid & 15, ty = tid >> 4;
    const int m0 = blockIdx.y << 7;
    const int n0 = blockIdx.x << 7;

    float acc[8][8];
#pragma unroll
    for (int i = 0; i < 8; i++)
#pragma unroll
        for (int j = 0; j < 8; j++) acc[i][j] = 0.f;

    const int lrow = tid >> 1;
    const int lkc  = (tid & 1) << 3;

    for (int kt = 0; kt < 1024; kt += 16) {
        float4 a0 = *(const float4*)(A + (size_t)(m0 + lrow) * 1024 + kt + lkc);
        float4 a1 = *(const float4*)(A + (size_t)(m0 + lrow) * 1024 + kt + lkc + 4);
        float4 b0 = *(const float4*)(W + (size_t)(n0 + lrow) * 1024 + kt + lkc);
        float4 b1 = *(const float4*)(W + (size_t)(n0 + lrow) * 1024 + kt + lkc + 4);
        As[lkc+0][lrow] = a0.x; As[lkc+1][lrow] = a0.y; As[lkc+2][lrow] = a0.z; As[lkc+3][lrow] = a0.w;
        As[lkc+4][lrow] = a1.x; As[lkc+5][lrow] = a1.y; As[lkc+6][lrow] = a1.z; As[lkc+7][lrow] = a1.w;
        Bs[lkc+0][lrow] = b0.x; Bs[lkc+1][lrow] = b0.y; Bs[lkc+2][lrow] = b0.z; Bs[lkc+3][lrow] = b0.w;
        Bs[lkc+4][lrow] = b1.x; Bs[lkc+5][lrow] = b1.y; Bs[lkc+6][lrow] = b1.z; Bs[lkc+7][lrow] = b1.w;
        __syncthreads();
#pragma unroll
        for (int k = 0; k < 16; k++) {
            float a[8], b[8];
            *(float4*)&a[0] = *(const float4*)&As[k][ty*8];
            *(float4*)&a[4] = *(const float4*)&As[k][ty*8+4];
            *(float4*)&b[0] = *(const float4*)&Bs[k][tx*8];
            *(float4*)&b[4] = *(const float4*)&Bs[k][tx*8+4];
#pragma unroll
            for (int i = 0; i < 8; i++)
#pragma unroll
                for (int j = 0; j < 8; j++)
                    acc[i][j] = fmaf(a[i], b[j], acc[i][j]);
        }
        __syncthreads();
    }

    // Scatter epilogue: n -> (which in {q,k,v}, head, dim); m -> (b, t)
#pragma unroll
    for (int i = 0; i < 8; i++) {
        int m  = m0 + ty*8 + i;
        int b_ = m >> 11;          // /2048
        int t  = m & 2047;
#pragma unroll
        for (int j = 0; j < 8; j++) {
            int n = n0 + tx*8 + j;
            int which = n >> 10;   // 0=q 1=k 2=v
            int c = n & 1023;
            int h = c >> 6, d = c & 63;
            float* dst = (which == 0) ? g_q : (which == 1 ? g_k : g_v);
            dst[((size_t)(b_*NH + h)*NT + t)*HD + d] = acc[i][j];
        }
    }
}

__global__ __launch_bounds__(256) void proj_gemm_kernel(
    const float* __restrict__ W, const float* __restrict__ bias,
    float* __restrict__ out)
{
    __shared__ float As[16][128];
    __shared__ float Bs[16][128];
    const int tid = threadIdx.x;
    const int tx = tid & 15, ty = tid >> 4;
    const int m0 = blockIdx.y << 7;
    const int n0 = blockIdx.x << 7;
    const float* A = g_att;

    float acc[8][8];
#pragma unroll
    for (int i = 0; i < 8; i++)
#pragma unroll
        for (int j = 0; j < 8; j++) acc[i][j] = 0.f;

    const int lrow = tid >> 1;
    const int lkc  = (tid & 1) << 3;

    for (int kt = 0; kt < 1024; kt += 16) {
        float4 a0 = *(const float4*)(A + (size_t)(m0 + lrow) * 1024 + kt + lkc);
        float4 a1 = *(const float4*)(A + (size_t)(m0 + lrow) * 1024 + kt + lkc + 4);
        float4 b0 = *(const float4*)(W + (size_t)(n0 + lrow) * 1024 + kt + lkc);
        float4 b1 = *(const float4*)(W + (size_t)(n0 + lrow) * 1024 + kt + lkc + 4);
        As[lkc+0][lrow] = a0.x; As[lkc+1][lrow] = a0.y; As[lkc+2][lrow] = a0.z; As[lkc+3][lrow] = a0.w;
        As[lkc+4][lrow] = a1.x; As[lkc+5][lrow] = a1.y; As[lkc+6][lrow] = a1.z; As[lkc+7][lrow] = a1.w;
        Bs[lkc+0][lrow] = b0.x; Bs[lkc+1][lrow] = b0.y; Bs[lkc+2][lrow] = b0.z; Bs[lkc+3][lrow] = b0.w;
        Bs[lkc+4][lrow] = b1.x; Bs[lkc+5][lrow] = b1.y; Bs[lkc+6][lrow] = b1.z; Bs[lkc+7][lrow] = b1.w;
        __syncthreads();
#pragma unroll
        for (int k = 0; k < 16; k++) {
            float a[8], b[8];
            *(float4*)&a[0] = *(const float4*)&As[k][ty*8];
            *(float4*)&a[4] = *(const float4*)&As[k][ty*8+4];
            *(float4*)&b[0] = *(const float4*)&Bs[k][tx*8];
            *(float4*)&b[4] = *(const float4*)&Bs[k][tx*8+4];
#pragma unroll
            for (int i = 0; i < 8; i++)
#pragma unroll
                for (int j = 0; j < 8; j++)
                    acc[i][j] = fmaf(a[i], b[j], acc[i][j]);
        }
        __syncthreads();
    }

#pragma unroll
    for (int i = 0; i < 8; i++) {
        int m = m0 + ty*8 + i;
#pragma unroll
        for (int j = 0; j < 8; j++) {
            int n = n0 + tx*8 + j;
            out[(size_t)m * 1024 + n] = acc[i][j] + bias[n];
        }
    }
}

// ---------------------------------------------------------------------------
// Flash attention (fp32): per block = one (b,h) x 64 query rows.
// Tiles of 64 kv rows, online softmax. Logit scale = +sqrt(hd) = 8 (faithful
// to reference, which multiplies instead of divides).
// smem: Q,K,V,P each [64][65] -> 66560 B dynamic.
// ---------------------------------------------------------------------------

__global__ __launch_bounds__(256) void attn_kernel()
{
    extern __shared__ float smv[];
    float* Qs = smv;              // [64][65]
    float* Ks = smv + 4160;
    float* Vs = smv + 8320;
    float* Ps = smv + 12480;

    const int tid = threadIdx.x;
    const int tx = tid & 15;      // 4 kv-cols / d-cols
    const int ty = tid >> 4;      // 4 q-rows
    const int bh = blockIdx.y;    // b*16+h
    const int qt = blockIdx.x;
    const int t0 = qt * 64;

    const float* qp = g_q + (size_t)bh * NT * HD + (size_t)t0 * HD;
    const float* kp = g_k + (size_t)bh * NT * HD;
    const float* vp = g_v + (size_t)bh * NT * HD;

    // Load Q tile (64x64): 4 float4 per thread
#pragma unroll
    for (int i = 0; i < 4; i++) {
        int id = tid + i * 256;
        int r = id >> 4;
        int c = (id & 15) << 2;
        float4 v = *(const float4*)(qp + r * 64 + c);
        Qs[r*65 + c + 0] = v.x; Qs[r*65 + c + 1] = v.y;
        Qs[r*65 + c + 2] = v.z; Qs[r*65 + c + 3] = v.w;
    }

    const float NEG_INF = -1e30f;
    float o[4][4];
    float m_i[4], l_i[4];
#pragma unroll
    for (int i = 0; i < 4; i++) {
        m_i[i] = NEG_INF; l_i[i] = 0.f;
#pragma unroll
        for (int j = 0; j < 4; j++) o[i][j] = 0.f;
    }

    for (int jt = 0; jt <= qt; jt++) {
        // Load K,V tiles
#pragma unroll
        for (int i = 0; i < 4; i++) {
            int id = tid + i * 256;
            int r = id >> 4;
            int c = (id & 15) << 2;
            float4 kk = *(const float4*)(kp + (size_t)(jt*64 + r) * 64 + c);
            Ks[r*65 + c + 0] = kk.x; Ks[r*65 + c + 1] = kk.y;
            Ks[r*65 + c + 2] = kk.z; Ks[r*65 + c + 3] = kk.w;
            float4 vv = *(const float4*)(vp + (size_t)(jt*64 + r) * 64 + c);
            Vs[r*65 + c + 0] = vv.x; Vs[r*65 + c + 1] = vv.y;
            Vs[r*65 + c + 2] = vv.z; Vs[r*65 + c + 3] = vv.w;
        }
        __syncthreads();

        // S = Q K^T
        float s[4][4];
#pragma unroll
        for (int i = 0; i < 4; i++)
#pragma unroll
            for (int j = 0; j < 4; j++) s[i][j] = 0.f;
        for (int d = 0; d < 64; d++) {
            float qv[4], kv[4];
#pragma unroll
            for (int i = 0; i < 4; i++) qv[i] = Qs[(ty*4 + i)*65 + d];
#pragma unroll
            for (int j = 0; j < 4; j++) kv[j] = Ks[(tx*4 + j)*65 + d];
#pragma unroll
            for (int i = 0; i < 4; i++)
#pragma unroll
                for (int j = 0; j < 4; j++)
                    s[i][j] = fmaf(qv[i], kv[j], s[i][j]);
        }

        // scale (x8, faithful) + causal mask on diagonal tile
        const bool diag = (jt == qt);
#pragma unroll
        for (int i = 0; i < 4; i++)
#pragma unroll
            for (int j = 0; j < 4; j++) {
                float v = s[i][j] * 8.0f;
                if (diag && (tx*4 + j > ty*4 + i)) v = NEG_INF;
                s[i][j] = v;
            }

        // row max (across 16 lanes of the row group)
        float rmax[4];
#pragma unroll
        for (int i = 0; i < 4; i++)
            rmax[i] = fmaxf(fmaxf(s[i][0], s[i][1]), fmaxf(s[i][2], s[i][3]));
#pragma unroll
        for (int off = 8; off >= 1; off >>= 1)
#pragma unroll
            for (int i = 0; i < 4; i++)
                rmax[i] = fmaxf(rmax[i], __shfl_xor_sync(0xffffffffu, rmax[i], off));

        float corr[4];
#pragma unroll
        for (int i = 0; i < 4; i++) {
            float mn = fmaxf(m_i[i], rmax[i]);
            corr[i] = __expf(m_i[i] - mn);
            m_i[i] = mn;
        }

        float rsum[4];
#pragma unroll
        for (int i = 0; i < 4; i++) {
            rsum[i] = 0.f;
#pragma unroll
            for (int j = 0; j < 4; j++) {
                float p = __expf(s[i][j] - m_i[i]);
                s[i][j] = p;
                rsum[i] += p;
            }
        }
#pragma unroll
        for (int off = 8; off >= 1; off >>= 1)
#pragma unroll
            for (int i = 0; i < 4; i++)
                rsum[i] += __shfl_xor_sync(0xffffffffu, rsum[i], off);

#pragma unroll
        for (int i = 0; i < 4; i++) {
            l_i[i] = l_i[i] * corr[i] + rsum[i];
#pragma unroll
            for (int j = 0; j < 4; j++) o[i][j] *= corr[i];
        }

        // publish P
#pragma unroll
        for (int i = 0; i < 4; i++)
#pragma unroll
            for (int j = 0; j < 4; j++)
                Ps[(ty*4 + i)*65 + tx*4 + j] = s[i][j];
        __syncthreads();

        // O += P V
        for (int kv = 0; kv < 64; kv++) {
            float pv[4], vv[4];
#pragma unroll
            for (int i = 0; i < 4; i++) pv[i] = Ps[(ty*4 + i)*65 + kv];
#pragma unroll
            for (int j = 0; j < 4; j++) vv[j] = Vs[kv*65 + tx*4 + j];
#pragma unroll
            for (int i = 0; i < 4; i++)
#pragma unroll
                for (int j = 0; j < 4; j++)
                    o[i][j] = fmaf(pv[i], vv[j], o[i][j]);
        }
        __syncthreads();
    }

    // normalize + write to [b*t][h*64+d] layout for proj GEMM
    const int b_ = bh >> 4;
    const int h  = bh & 15;
#pragma unroll
    for (int i = 0; i < 4; i++) {
        float inv = 1.0f / l_i[i];
        int t = t0 + ty*4 + i;
#pragma unroll
        for (int j = 0; j < 4; j++)
            g_att[(size_t)(b_*NT + t) * NC + h*HD + tx*4 + j] = o[i][j] * inv;
    }
}

// ---------------------------------------------------------------------------

extern "C" void kernel_launch(void* const* d_in, const int* in_sizes, int n_in,
                              void* d_out, int out_size)
{
    const float* x      = (const float*)d_in[0];
    const float* W_attn = (const float*)d_in[1];
    const float* W_proj = (const float*)d_in[2];
    const float* b_proj = (const float*)d_in[3];
    float* out = (float*)d_out;

    // dynamic smem opt-in for attention (66560 B > 48K default)
    cudaFuncSetAttribute(attn_kernel,
                         cudaFuncAttributeMaxDynamicSharedMemorySize, 66560);

    qkv_gemm_kernel<<<dim3(24, 64), 256>>>(x, W_attn);
    attn_kernel<<<dim3(32, 64), 256, 66560>>>();
    proj_gemm_kernel<<<dim3(8, 64), 256>>>(W_proj, b_proj, out);
}

// round 2
// speedup vs baseline: 1.0003x; 1.0003x over previous
#include <cuda_runtime.h>
#include <math.h>

#define NB 4
#define NT 2048
#define NC 1024
#define NH 16
#define HD 64
#define MM (NB*NT)          // 8192 rows

// Scratch (device globals: allowed; no runtime allocation)
__device__ float g_q[(size_t)NB*NH*NT*HD];   // [b][h][t][d]
__device__ float g_k[(size_t)NB*NH*NT*HD];
__device__ float g_v[(size_t)NB*NH*NT*HD];
__device__ float g_att[(size_t)MM*NC];       // [b*t][h*64+d]

// ---------------------------------------------------------------------------
// GEMM: C[m][n] = sum_k A[m][k] * W[n][k]   (A row-major MxK, W row-major NxK)
// BM=BN=128, BK=16, 256 threads, 8x8 per-thread tile.
// ---------------------------------------------------------------------------

__global__ __launch_bounds__(256) void qkv_gemm_kernel(
    const float* __restrict__ A, const float* __restrict__ W)
{
    __shared__ float As[16][128];
    __shared__ float Bs[16][128];
    const int tid = threadIdx.x;
    const int tx = tid & 15, ty = tid >> 4;
    const int m0 = blockIdx.y << 7;
    const int n0 = blockIdx.x << 7;

    float acc[8][8];
#pragma unroll
    for (int i = 0; i < 8; i++)
#pragma unroll
        for (int j = 0; j < 8; j++) acc[i][j] = 0.f;

    const int lrow = tid >> 1;
    const int lkc  = (tid & 1) << 3;

    for (int kt = 0; kt < 1024; kt += 16) {
        float4 a0 = *(const float4*)(A + (size_t)(m0 + lrow) * 1024 + kt + lkc);
        float4 a1 = *(const float4*)(A + (size_t)(m0 + lrow) * 1024 + kt + lkc + 4);
        float4 b0 = *(const float4*)(W + (size_t)(n0 + lrow) * 1024 + kt + lkc);
        float4 b1 = *(const float4*)(W + (size_t)(n0 + lrow) * 1024 + kt + lkc + 4);
        As[lkc+0][lrow] = a0.x; As[lkc+1][lrow] = a0.y; As[lkc+2][lrow] = a0.z; As[lkc+3][lrow] = a0.w;
        As[lkc+4][lrow] = a1.x; As[lkc+5][lrow] = a1.y; As[lkc+6][lrow] = a1.z; As[lkc+7][lrow] = a1.w;
        Bs[lkc+0][lrow] = b0.x; Bs[lkc+1][lrow] = b0.y; Bs[lkc+2][lrow] = b0.z; Bs[lkc+3][lrow] = b0.w;
        Bs[lkc+4][lrow] = b1.x; Bs[lkc+5][lrow] = b1.y; Bs[lkc+6][lrow] = b1.z; Bs[lkc+7][lrow] = b1.w;
        __syncthreads();
#pragma unroll
        for (int k = 0; k < 16; k++) {
            float a[8], b[8];
            *(float4*)&a[0] = *(const float4*)&As[k][ty*8];
            *(float4*)&a[4] = *(const float4*)&As[k][ty*8+4];
            *(float4*)&b[0] = *(const float4*)&Bs[k][tx*8];
            *(float4*)&b[4] = *(const float4*)&Bs[k][tx*8+4];
#pragma unroll
            for (int i = 0; i < 8; i++)
#pragma unroll
                for (int j = 0; j < 8; j++)
                    acc[i][j] = fmaf(a[i], b[j], acc[i][j]);
        }
        __syncthreads();
    }

    // Scatter epilogue: n -> (which in {q,k,v}, head, dim); m -> (b, t)
#pragma unroll
    for (int i = 0; i < 8; i++) {
        int m  = m0 + ty*8 + i;
        int b_ = m >> 11;          // /2048
        int t  = m & 2047;
#pragma unroll
        for (int j = 0; j < 8; j++) {
            int n = n0 + tx*8 + j;
            int which = n >> 10;   // 0=q 1=k 2=v
            int c = n & 1023;
            int h = c >> 6, d = c & 63;
            float* dst = (which == 0) ? g_q : (which == 1 ? g_k : g_v);
            dst[((size_t)(b_*NH + h)*NT + t)*HD + d] = acc[i][j];
        }
    }
}

__global__ __launch_bounds__(256) void proj_gemm_kernel(
    const float* __restrict__ W, const float* __restrict__ bias,
    float* __restrict__ out)
{
    __shared__ float As[16][128];
    __shared__ float Bs[16][128];
    const int tid = threadIdx.x;
    const int tx = tid & 15, ty = tid >> 4;
    const int m0 = blockIdx.y << 7;
    const int n0 = blockIdx.x << 7;
    const float* A = g_att;

    float acc[8][8];
#pragma unroll
    for (int i = 0; i < 8; i++)
#pragma unroll
        for (int j = 0; j < 8; j++) acc[i][j] = 0.f;

    const int lrow = tid >> 1;
    const int lkc  = (tid & 1) << 3;

    for (int kt = 0; kt < 1024; kt += 16) {
        float4 a0 = *(const float4*)(A + (size_t)(m0 + lrow) * 1024 + kt + lkc);
        float4 a1 = *(const float4*)(A + (size_t)(m0 + lrow) * 1024 + kt + lkc + 4);
        float4 b0 = *(const float4*)(W + (size_t)(n0 + lrow) * 1024 + kt + lkc);
        float4 b1 = *(const float4*)(W + (size_t)(n0 + lrow) * 1024 + kt + lkc + 4);
        As[lkc+0][lrow] = a0.x; As[lkc+1][lrow] = a0.y; As[lkc+2][lrow] = a0.z; As[lkc+3][lrow] = a0.w;
        As[lkc+4][lrow] = a1.x; As[lkc+5][lrow] = a1.y; As[lkc+6][lrow] = a1.z; As[lkc+7][lrow] = a1.w;
        Bs[lkc+0][lrow] = b0.x; Bs[lkc+1][lrow] = b0.y; Bs[lkc+2][lrow] = b0.z; Bs[lkc+3][lrow] = b0.w;
        Bs[lkc+4][lrow] = b1.x; Bs[lkc+5][lrow] = b1.y; Bs[lkc+6][lrow] = b1.z; Bs[lkc+7][lrow] = b1.w;
        __syncthreads();
#pragma unroll
        for (int k = 0; k < 16; k++) {
            float a[8], b[8];
            *(float4*)&a[0] = *(const float4*)&As[k][ty*8];
            *(float4*)&a[4] = *(const float4*)&As[k][ty*8+4];
            *(float4*)&b[0] = *(const float4*)&Bs[k][tx*8];
            *(float4*)&b[4] = *(const float4*)&Bs[k][tx*8+4];
#pragma unroll
            for (int i = 0; i < 8; i++)
#pragma unroll
                for (int j = 0; j < 8; j++)
                    acc[i][j] = fmaf(a[i], b[j], acc[i][j]);
        }
        __syncthreads();
    }

#pragma unroll
    for (int i = 0; i < 8; i++) {
        int m = m0 + ty*8 + i;
#pragma unroll
        for (int j = 0; j < 8; j++) {
            int n = n0 + tx*8 + j;
            out[(size_t)m * 1024 + n] = acc[i][j] + bias[n];
        }
    }
}

// ---------------------------------------------------------------------------
// Flash attention (fp32): per block = one (b,h) x 64 query rows.
// Tiles of 64 kv rows, online softmax. Logit scale = +sqrt(hd) = 8 (faithful
// to reference, which multiplies instead of divides).
// smem: Q,K,V,P each [64][65] -> 66560 B dynamic.
// ---------------------------------------------------------------------------

__global__ __launch_bounds__(256) void attn_kernel()
{
    extern __shared__ float smv[];
    float* Qs = smv;              // [64][65]
    float* Ks = smv + 4160;
    float* Vs = smv + 8320;
    float* Ps = smv + 12480;

    const int tid = threadIdx.x;
    const int tx = tid & 15;      // 4 kv-cols / d-cols
    const int ty = tid >> 4;      // 4 q-rows
    const int bh = blockIdx.y;    // b*16+h
    const int qt = blockIdx.x;
    const int t0 = qt * 64;

    const float* qp = g_q + (size_t)bh * NT * HD + (size_t)t0 * HD;
    const float* kp = g_k + (size_t)bh * NT * HD;
    const float* vp = g_v + (size_t)bh * NT * HD;

    // Load Q tile (64x64): 4 float4 per thread
#pragma unroll
    for (int i = 0; i < 4; i++) {
        int id = tid + i * 256;
        int r = id >> 4;
        int c = (id & 15) << 2;
        float4 v = *(const float4*)(qp + r * 64 + c);
        Qs[r*65 + c + 0] = v.x; Qs[r*65 + c + 1] = v.y;
        Qs[r*65 + c + 2] = v.z; Qs[r*65 + c + 3] = v.w;
    }

    const float NEG_INF = -1e30f;
    float o[4][4];
    float m_i[4], l_i[4];
#pragma unroll
    for (int i = 0; i < 4; i++) {
        m_i[i] = NEG_INF; l_i[i] = 0.f;
#pragma unroll
        for (int j = 0; j < 4; j++) o[i][j] = 0.f;
    }

    for (int jt = 0; jt <= qt; jt++) {
        // Load K,V tiles
#pragma unroll
        for (int i = 0; i < 4; i++) {
            int id = tid + i * 256;
            int r = id >> 4;
            int c = (id & 15) << 2;
            float4 kk = *(const float4*)(kp + (size_t)(jt*64 + r) * 64 + c);
            Ks[r*65 + c + 0] = kk.x; Ks[r*65 + c + 1] = kk.y;
            Ks[r*65 + c + 2] = kk.z; Ks[r*65 + c + 3] = kk.w;
            float4 vv = *(const float4*)(vp + (size_t)(jt*64 + r) * 64 + c);
            Vs[r*65 + c + 0] = vv.x; Vs[r*65 + c + 1] = vv.y;
            Vs[r*65 + c + 2] = vv.z; Vs[r*65 + c + 3] = vv.w;
        }
        __syncthreads();

        // S = Q K^T
        float s[4][4];
#pragma unroll
        for (int i = 0; i < 4; i++)
#pragma unroll
            for (int j = 0; j < 4; j++) s[i][j] = 0.f;
        for (int d = 0; d < 64; d++) {
            float qv[4], kv[4];
#pragma unroll
            for (int i = 0; i < 4; i++) qv[i] = Qs[(ty*4 + i)*65 + d];
#pragma unroll
            for (int j = 0; j < 4; j++) kv[j] = Ks[(tx*4 + j)*65 + d];
#pragma unroll
            for (int i = 0; i < 4; i++)
#pragma unroll
                for (int j = 0; j < 4; j++)
                    s[i][j] = fmaf(qv[i], kv[j], s[i][j]);
        }

        // scale (x8, faithful) + causal mask on diagonal tile
        const bool diag = (jt == qt);
#pragma unroll
        for (int i = 0; i < 4; i++)
#pragma unroll
            for (int j = 0; j < 4; j++) {
                float v = s[i][j] * 8.0f;
                if (diag && (tx*4 + j > ty*4 + i)) v = NEG_INF;
                s[i][j] = v;
            }

        // row max (across 16 lanes of the row group)
        float rmax[4];
#pragma unroll
        for (int i = 0; i < 4; i++)
            rmax[i] = fmaxf(fmaxf(s[i][0], s[i][1]), fmaxf(s[i][2], s[i][3]));
#pragma unroll
        for (int off = 8; off >= 1; off >>= 1)
#pragma unroll
            for (int i = 0; i < 4; i++)
                rmax[i] = fmaxf(rmax[i], __shfl_xor_sync(0xffffffffu, rmax[i], off));

        float corr[4];
#pragma unroll
        for (int i = 0; i < 4; i++) {
            float mn = fmaxf(m_i[i], rmax[i]);
            corr[i] = __expf(m_i[i] - mn);
            m_i[i] = mn;
        }

        float rsum[4];
#pragma unroll
        for (int i = 0; i < 4; i++) {
            rsum[i] = 0.f;
#pragma unroll
            for (int j = 0; j < 4; j++) {
                float p = __expf(s[i][j] - m_i[i]);
                s[i][j] = p;
                rsum[i] += p;
            }
        }
#pragma unroll
        for (int off = 8; off >= 1; off >>= 1)
#pragma unroll
            for (int i = 0; i < 4; i++)
                rsum[i] += __shfl_xor_sync(0xffffffffu, rsum[i], off);

#pragma unroll
        for (int i = 0; i < 4; i++) {
            l_i[i] = l_i[i] * corr[i] + rsum[i];
#pragma unroll
            for (int j = 0; j < 4; j++) o[i][j] *= corr[i];
        }

        // publish P
#pragma unroll
        for (int i = 0; i < 4; i++)
#pragma unroll
            for (int j = 0; j < 4; j++)
                Ps[(ty*4 + i)*65 + tx*4 + j] = s[i][j];
        __syncthreads();

        // O += P V
        for (int kv = 0; kv < 64; kv++) {
            float pv[4], vv[4];
#pragma unroll
            for (int i = 0; i < 4; i++) pv[i] = Ps[(ty*4 + i)*65 + kv];
#pragma unroll
            for (int j = 0; j < 4; j++) vv[j] = Vs[kv*65 + tx*4 + j];
#pragma unroll
            for (int i = 0; i < 4; i++)
#pragma unroll
                for (int j = 0; j < 4; j++)
                    o[i][j] = fmaf(pv[i], vv[j], o[i][j]);
        }
        __syncthreads();
    }

    // normalize + write to [b*t][h*64+d] layout for proj GEMM
    const int b_ = bh >> 4;
    const int h  = bh & 15;
#pragma unroll
    for (int i = 0; i < 4; i++) {
        float inv = 1.0f / l_i[i];
        int t = t0 + ty*4 + i;
#pragma unroll
        for (int j = 0; j < 4; j++)
            g_att[(size_t)(b_*NT + t) * NC + h*HD + tx*4 + j] = o[i][j] * inv;
    }
}

// ---------------------------------------------------------------------------

extern "C" void kernel_launch(void* const* d_in, const int* in_sizes, int n_in,
                              void* d_out, int out_size)
{
    const float* x      = (const float*)d_in[0];
    const float* W_attn = (const float*)d_in[1];
    const float* W_proj = (const float*)d_in[2];
    const float* b_proj = (const float*)d_in[3];
    float* out = (float*)d_out;

    // dynamic smem opt-in for attention (66560 B > 48K default)
    cudaFuncSetAttribute(attn_kernel,
                         cudaFuncAttributeMaxDynamicSharedMemorySize, 66560);

    qkv_gemm_kernel<<<dim3(24, 64), 256>>>(x, W_attn);
    attn_kernel<<<dim3(32, 64), 256, 66560>>>();
    proj_gemm_kernel<<<dim3(8, 64), 256>>>(W_proj, b_proj, out);
}

// round 3
// speedup vs baseline: 1.5396x; 1.5392x over previous
#include <cuda_runtime.h>
#include <cuda_bf16.h>
#include <mma.h>
#include <math.h>

using namespace nvcuda;

#define NB 4
#define NT 2048
#define NC 1024
#define NH 16
#define HD 64
#define MM (NB*NT)          // 8192

// Scratch device globals (no runtime allocation allowed)
__device__ float g_qkv[(size_t)MM * 3 * NC];   // [b*t][3C]
__device__ float g_att[(size_t)MM * NC];       // [b*t][h*64+d]

// Split fp32 -> bf16 hi + bf16 lo, packed pair stores
__device__ __forceinline__ void split_store2(float x, float y,
                                             __nv_bfloat16* hp, __nv_bfloat16* lp)
{
    __nv_bfloat16 hx = __float2bfloat16(x);
    __nv_bfloat16 hy = __float2bfloat16(y);
    float rx = x - __bfloat162float(hx);
    float ry = y - __bfloat162float(hy);
    *(__nv_bfloat162*)hp = __halves2bfloat162(hx, hy);
    *(__nv_bfloat162*)lp = __halves2bfloat162(__float2bfloat16(rx), __float2bfloat16(ry));
}

// ---------------------------------------------------------------------------
// GEMM: C[m][n] = sum_k A[m][k] * W[n][k], K=1024 fixed.
// bf16 split (3 mma passes), 128x128 block tile, 8 warps, warp = 64x32.
// ---------------------------------------------------------------------------
#define GLD 40   // smem ld (bf16 elems) for 32-col chunk, padded

__global__ __launch_bounds__(256) void gemm_bf16s_kernel(
    const float* __restrict__ A, const float* __restrict__ W,
    float* __restrict__ C, int ldc)
{
    __shared__ __nv_bfloat16 Ah[128*GLD], Al[128*GLD], Bh[128*GLD], Bl[128*GLD];

    const int tid  = threadIdx.x;
    const int warp = tid >> 5;
    const int m0 = blockIdx.y << 7;
    const int n0 = blockIdx.x << 7;
    const int mw = (warp >> 2) * 64;   // 0 or 64
    const int nw = (warp & 3) * 32;    // 0,32,64,96

    wmma::fragment<wmma::accumulator, 16,16,16, float> acc[4][2];
#pragma unroll
    for (int i = 0; i < 4; i++)
#pragma unroll
        for (int j = 0; j < 2; j++) wmma::fill_fragment(acc[i][j], 0.0f);

    const int lr = tid >> 1;          // 0..127
    const int lc = (tid & 1) << 4;    // 0 or 16

    for (int kt = 0; kt < 1024; kt += 32) {
        const float* ap = A + (size_t)(m0 + lr) * 1024 + kt + lc;
        const float* bp = W + (size_t)(n0 + lr) * 1024 + kt + lc;
#pragma unroll
        for (int u = 0; u < 4; u++) {
            float4 av = *(const float4*)(ap + u * 4);
            float4 bv = *(const float4*)(bp + u * 4);
            int o = lr * GLD + lc + u * 4;
            split_store2(av.x, av.y, &Ah[o],   &Al[o]);
            split_store2(av.z, av.w, &Ah[o+2], &Al[o+2]);
            split_store2(bv.x, bv.y, &Bh[o],   &Bl[o]);
            split_store2(bv.z, bv.w, &Bh[o+2], &Bl[o+2]);
        }
        __syncthreads();

#pragma unroll
        for (int kk = 0; kk < 2; kk++) {
            wmma::fragment<wmma::matrix_a, 16,16,16, __nv_bfloat16, wmma::row_major> ah[4], al[4];
#pragma unroll
            for (int i = 0; i < 4; i++) {
                wmma::load_matrix_sync(ah[i], Ah + (mw + i*16) * GLD + kk*16, GLD);
                wmma::load_matrix_sync(al[i], Al + (mw + i*16) * GLD + kk*16, GLD);
            }
#pragma unroll
            for (int j = 0; j < 2; j++) {
                wmma::fragment<wmma::matrix_b, 16,16,16, __nv_bfloat16, wmma::col_major> bh, bl;
                wmma::load_matrix_sync(bh, Bh + (nw + j*16) * GLD + kk*16, GLD);
                wmma::load_matrix_sync(bl, Bl + (nw + j*16) * GLD + kk*16, GLD);
#pragma unroll
                for (int i = 0; i < 4; i++) {
                    wmma::mma_sync(acc[i][j], ah[i], bh, acc[i][j]);
                    wmma::mma_sync(acc[i][j], ah[i], bl, acc[i][j]);
                    wmma::mma_sync(acc[i][j], al[i], bh, acc[i][j]);
                }
            }
        }
        __syncthreads();
    }

#pragma unroll
    for (int i = 0; i < 4; i++)
#pragma unroll
        for (int j = 0; j < 2; j++)
            wmma::store_matrix_sync(C + (size_t)(m0 + mw + i*16) * ldc + n0 + nw + j*16,
                                    acc[i][j], ldc, wmma::mem_row_major);
}

__global__ void bias_add_kernel(float* __restrict__ out, const float* __restrict__ bias)
{
    int idx = blockIdx.x * blockDim.x + threadIdx.x;   // float4 index
    float4 v = ((float4*)out)[idx];
    int c = (idx << 2) & 1023;
    v.x += bias[c]; v.y += bias[c+1]; v.z += bias[c+2]; v.w += bias[c+3];
    ((float4*)out)[idx] = v;
}

// ---------------------------------------------------------------------------
// Flash attention with wmma bf16-split for QK^T and P·V.
// One block = (b,h) x 64 query rows. 256 threads = 8 warps.
// ---------------------------------------------------------------------------
#define ALDB 72   // bf16 smem ld
#define ALDS 68   // f32 smem ld
#define ATT_SMEM (8*64*ALDB*2 + 2*64*ALDS*4 + 3*64*4)   // 109312 bytes

__global__ __launch_bounds__(256) void attn_wmma_kernel()
{
    extern __shared__ char smraw[];
    __nv_bfloat16* Qh = (__nv_bfloat16*)smraw;
    __nv_bfloat16* Ql = Qh + 64*ALDB;
    __nv_bfloat16* Kh = Ql + 64*ALDB;
    __nv_bfloat16* Kl = Kh + 64*ALDB;
    __nv_bfloat16* Vh = Kl + 64*ALDB;
    __nv_bfloat16* Vl = Vh + 64*ALDB;
    __nv_bfloat16* Ph = Vl + 64*ALDB;
    __nv_bfloat16* Pl = Ph + 64*ALDB;
    float* S    = (float*)(Pl + 64*ALDB);   // also Otile staging
    float* O    = S + 64*ALDS;
    float* m_s  = O + 64*ALDS;
    float* l_s  = m_s + 64;
    float* c_s  = l_s + 64;

    const int tid  = threadIdx.x;
    const int warp = tid >> 5;
    const int bh = blockIdx.y;
    const int qt = blockIdx.x;
    const int t0 = qt * 64;
    const int b_ = bh >> 4;
    const int h  = bh & 15;

    const int r  = tid >> 2;          // 0..63 (row for loads/softmax/merge)
    const int cq = (tid & 3) << 4;    // col base 0/16/32/48

    // Load Q tile once (q at col offset 0 in qkv)
    {
        const float* qp = g_qkv + (size_t)(b_*NT + t0 + r) * 3072 + h*HD + cq;
#pragma unroll
        for (int u = 0; u < 4; u++) {
            float4 v = *(const float4*)(qp + u*4);
            int o = r*ALDB + cq + u*4;
            split_store2(v.x, v.y, &Qh[o],   &Ql[o]);
            split_store2(v.z, v.w, &Qh[o+2], &Ql[o+2]);
        }
    }
    // init O, stats
#pragma unroll
    for (int u = 0; u < 4; u++) {
        int o = r*ALDS + cq + u*4;
        O[o] = 0.f; O[o+1] = 0.f; O[o+2] = 0.f; O[o+3] = 0.f;
    }
    if (tid < 64) { m_s[tid] = -1e30f; l_s[tid] = 0.f; }

    const int mw = warp >> 1;           // 0..3  (16-row tile)
    const int nb = (warp & 1) * 2;      // 0 or 2 (base of 2 n-tiles)

    for (int jt = 0; jt <= qt; jt++) {
        // Load K,V tiles
        {
            const float* kp = g_qkv + (size_t)(b_*NT + jt*64 + r) * 3072 + 1024 + h*HD + cq;
            const float* vp = kp + 1024;
#pragma unroll
            for (int u = 0; u < 4; u++) {
                float4 kv = *(const float4*)(kp + u*4);
                float4 vv = *(const float4*)(vp + u*4);
                int o = r*ALDB + cq + u*4;
                split_store2(kv.x, kv.y, &Kh[o],   &Kl[o]);
                split_store2(kv.z, kv.w, &Kh[o+2], &Kl[o+2]);
                split_store2(vv.x, vv.y, &Vh[o],   &Vl[o]);
                split_store2(vv.z, vv.w, &Vh[o+2], &Vl[o+2]);
            }
        }
        __syncthreads();

        // S = Q K^T  (warp computes 16x32 of the 64x64 tile)
        {
            wmma::fragment<wmma::accumulator,16,16,16,float> sacc[2];
            wmma::fill_fragment(sacc[0], 0.f);
            wmma::fill_fragment(sacc[1], 0.f);
#pragma unroll
            for (int kk = 0; kk < 4; kk++) {
                wmma::fragment<wmma::matrix_a,16,16,16,__nv_bfloat16,wmma::row_major> ah, al;
                wmma::load_matrix_sync(ah, Qh + (mw*16)*ALDB + kk*16, ALDB);
                wmma::load_matrix_sync(al, Ql + (mw*16)*ALDB + kk*16, ALDB);
#pragma unroll
                for (int j = 0; j < 2; j++) {
                    int n = nb + j;
                    wmma::fragment<wmma::matrix_b,16,16,16,__nv_bfloat16,wmma::col_major> bhf, blf;
                    wmma::load_matrix_sync(bhf, Kh + (n*16)*ALDB + kk*16, ALDB);
                    wmma::load_matrix_sync(blf, Kl + (n*16)*ALDB + kk*16, ALDB);
                    wmma::mma_sync(sacc[j], ah, bhf, sacc[j]);
                    wmma::mma_sync(sacc[j], ah, blf, sacc[j]);
                    wmma::mma_sync(sacc[j], al, bhf, sacc[j]);
                }
            }
            wmma::store_matrix_sync(S + (mw*16)*ALDS + nb*16,      sacc[0], ALDS, wmma::mem_row_major);
            wmma::store_matrix_sync(S + (mw*16)*ALDS + (nb+1)*16,  sacc[1], ALDS, wmma::mem_row_major);
        }
        __syncthreads();

        // softmax step (rows owned by quads of threads)
        {
            const bool diag = (jt == qt);
            float v[16];
            float mx = -1e30f;
#pragma unroll
            for (int c = 0; c < 16; c++) {
                float s = S[r*ALDS + cq + c] * 8.0f;
                if (diag && (cq + c > r)) s = -1e30f;
                v[c] = s;
                mx = fmaxf(mx, s);
            }
            mx = fmaxf(mx, __shfl_xor_sync(0xffffffffu, mx, 1));
            mx = fmaxf(mx, __shfl_xor_sync(0xffffffffu, mx, 2));
            float mold = m_s[r];
            float mnew = fmaxf(mold, mx);
            float rsum = 0.f;
#pragma unroll
            for (int c = 0; c < 16; c += 2) {
                float p0 = __expf(v[c]   - mnew);
                float p1 = __expf(v[c+1] - mnew);
                rsum += p0 + p1;
                int o = r*ALDB + cq + c;
                split_store2(p0, p1, &Ph[o], &Pl[o]);
            }
            rsum += __shfl_xor_sync(0xffffffffu, rsum, 1);
            rsum += __shfl_xor_sync(0xffffffffu, rsum, 2);
            if ((tid & 3) == 0) {
                float corr = __expf(mold - mnew);
                c_s[r] = corr;
                m_s[r] = mnew;
                l_s[r] = l_s[r] * corr + rsum;
            }
        }
        __syncthreads();

        // Otile = P V  (into S staging)
        {
            wmma::fragment<wmma::accumulator,16,16,16,float> oacc[2];
            wmma::fill_fragment(oacc[0], 0.f);
            wmma::fill_fragment(oacc[1], 0.f);
#pragma unroll
            for (int kk = 0; kk < 4; kk++) {
                wmma::fragment<wmma::matrix_a,16,16,16,__nv_bfloat16,wmma::row_major> ah, al;
                wmma::load_matrix_sync(ah, Ph + (mw*16)*ALDB + kk*16, ALDB);
                wmma::load_matrix_sync(al, Pl + (mw*16)*ALDB + kk*16, ALDB);
#pragma unroll
                for (int j = 0; j < 2; j++) {
                    int n = nb + j;
                    wmma::fragment<wmma::matrix_b,16,16,16,__nv_bfloat16,wmma::row_major> bhf, blf;
                    wmma::load_matrix_sync(bhf, Vh + (kk*16)*ALDB + n*16, ALDB);
                    wmma::load_matrix_sync(blf, Vl + (kk*16)*ALDB + n*16, ALDB);
                    wmma::mma_sync(oacc[j], ah, bhf, oacc[j]);
                    wmma::mma_sync(oacc[j], ah, blf, oacc[j]);
                    wmma::mma_sync(oacc[j], al, bhf, oacc[j]);
                }
            }
            wmma::store_matrix_sync(S + (mw*16)*ALDS + nb*16,      oacc[0], ALDS, wmma::mem_row_major);
            wmma::store_matrix_sync(S + (mw*16)*ALDS + (nb+1)*16,  oacc[1], ALDS, wmma::mem_row_major);
        }
        __syncthreads();

        // merge running O
        {
            float corr = c_s[r];
#pragma unroll
            for (int u = 0; u < 16; u += 4) {
                int o = r*ALDS + cq + u;
                O[o]   = O[o]   * corr + S[o];
                O[o+1] = O[o+1] * corr + S[o+1];
                O[o+2] = O[o+2] * corr + S[o+2];
                O[o+3] = O[o+3] * corr + S[o+3];
            }
        }
        // next-iter K/V overwrite is fenced by the sync after their load
    }

    // normalize + write (same thread->row mapping as merge: no sync needed)
    {
        float inv = 1.0f / l_s[r];
        float* op = g_att + (size_t)(b_*NT + t0 + r) * NC + h*HD + cq;
#pragma unroll
        for (int u = 0; u < 16; u++)
            op[u] = O[r*ALDS + cq + u] * inv;
    }
}

// ---------------------------------------------------------------------------

extern "C" void kernel_launch(void* const* d_in, const int* in_sizes, int n_in,
                              void* d_out, int out_size)
{
    const float* x      = (const float*)d_in[0];
    const float* W_attn = (const float*)d_in[1];
    const float* W_proj = (const float*)d_in[2];
    const float* b_proj = (const float*)d_in[3];
    float* out = (float*)d_out;

    float* qkv_ptr; cudaGetSymbolAddress((void**)&qkv_ptr, g_qkv);
    float* att_ptr; cudaGetSymbolAddress((void**)&att_ptr, g_att);

    cudaFuncSetAttribute(attn_wmma_kernel,
                         cudaFuncAttributeMaxDynamicSharedMemorySize, ATT_SMEM);

    // QKV: [8192,1024] x [3072,1024]^T -> [8192,3072]
    gemm_bf16s_kernel<<<dim3(24, 64), 256>>>(x, W_attn, qkv_ptr, 3072);
    // attention
    attn_wmma_kernel<<<dim3(32, 64), 256, ATT_SMEM>>>();
    // proj: [8192,1024] x [1024,1024]^T -> [8192,1024]
    gemm_bf16s_kernel<<<dim3(8, 64), 256>>>(att_ptr, W_proj, out, 1024);
    bias_add_kernel<<<MM, 256>>>(out, b_proj);
}

// round 5
// speedup vs baseline: 1.7685x; 1.1487x over previous
#include <cuda_runtime.h>
#include <cuda_bf16.h>
#include <mma.h>
#include <math.h>
#include <cstdint>

using namespace nvcuda;

#define NB 4
#define NT 2048
#define NC 1024
#define NH 16
#define HD 64
#define MM (NB*NT)          // 8192

// ---------------- global scratch (device globals; no runtime alloc) --------
__device__ __nv_bfloat16 g_xh[(size_t)MM*NC],    g_xl[(size_t)MM*NC];
__device__ __nv_bfloat16 g_wah[(size_t)3*NC*NC], g_wal[(size_t)3*NC*NC];
__device__ __nv_bfloat16 g_wph[(size_t)NC*NC],   g_wpl[(size_t)NC*NC];
__device__ __nv_bfloat16 g_qkvh[(size_t)MM*3*NC],g_qkvl[(size_t)MM*3*NC];
__device__ __nv_bfloat16 g_atth[(size_t)MM*NC],  g_attl[(size_t)MM*NC];

// ---------------- helpers --------------------------------------------------
__device__ __forceinline__ uint32_t s2u(const void* p) {
    return (uint32_t)__cvta_generic_to_shared(p);
}
__device__ __forceinline__ void cp16(uint32_t dst, const void* src) {
    asm volatile("cp.async.cg.shared.global [%0], [%1], 16;" :: "r"(dst), "l"(src));
}
__device__ __forceinline__ void cp_commit() {
    asm volatile("cp.async.commit_group;" ::: "memory");
}
__device__ __forceinline__ void cp_wait1() {
    asm volatile("cp.async.wait_group 1;" ::: "memory");
}
__device__ __forceinline__ void cp_wait0() {
    asm volatile("cp.async.wait_group 0;" ::: "memory");
}

// Split fp32 -> bf16 hi + bf16 lo, packed pair stores
__device__ __forceinline__ void split_store2(float x, float y,
                                             __nv_bfloat16* hp, __nv_bfloat16* lp)
{
    __nv_bfloat16 hx = __float2bfloat16(x);
    __nv_bfloat16 hy = __float2bfloat16(y);
    float rx = x - __bfloat162float(hx);
    float ry = y - __bfloat162float(hy);
    *(__nv_bfloat162*)hp = __halves2bfloat162(hx, hy);
    *(__nv_bfloat162*)lp = __halves2bfloat162(__float2bfloat16(rx), __float2bfloat16(ry));
}

// ---------------- split kernel (f32 -> bf16 hi/lo) -------------------------
__global__ __launch_bounds__(256) void split_kernel(
    const float4* __restrict__ src, __nv_bfloat16* __restrict__ dh,
    __nv_bfloat16* __restrict__ dl, int n4)
{
    int i = blockIdx.x * 256 + threadIdx.x;
    if (i >= n4) return;
    float4 v = src[i];
    split_store2(v.x, v.y, dh + (size_t)i*4,     dl + (size_t)i*4);
    split_store2(v.z, v.w, dh + (size_t)i*4 + 2, dl + (size_t)i*4 + 2);
}

// ---------------------------------------------------------------------------
// wmma GEMM on pre-split bf16: C[m][n] = sum_k A[m][k]*B[n][k], K=1024.
// CTA 128x128, BK=32, 256 thr (8 warps, warp = 64x32), cp.async dbl-buffer.
// 3-pass split: Ah*Bh + Ah*Bl + Al*Bh into one f32 accumulator.
// mode 0: bf16 hi/lo out.  mode 1: f32 + bias out.
// ---------------------------------------------------------------------------
#define GLD 40                    // smem leading dim (bf16), row = 80 B
#define GT_BYTES (128*GLD*2)      // 10240 per tile
#define GSTAGE   (4*GT_BYTES)     // 40960 per stage (Ah,Al,Bh,Bl)
#define GEMM_SMEM (2*GSTAGE)      // 81920 (also reused as f32 epilogue staging)
#define ELD 132                   // f32 staging leading dim

__device__ __forceinline__ void g_load_stage(
    uint32_t sbase, int st, int kt, int m0, int n0, int tid,
    const __nv_bfloat16* __restrict__ Ah, const __nv_bfloat16* __restrict__ Al,
    const __nv_bfloat16* __restrict__ Bh, const __nv_bfloat16* __restrict__ Bl)
{
    const __nv_bfloat16* srcs[4];
    srcs[0] = Ah + (size_t)m0 * 1024 + kt * 32;
    srcs[1] = Al + (size_t)m0 * 1024 + kt * 32;
    srcs[2] = Bh + (size_t)n0 * 1024 + kt * 32;
    srcs[3] = Bl + (size_t)n0 * 1024 + kt * 32;
#pragma unroll
    for (int b = 0; b < 4; b++) {
        uint32_t dbase = sbase + st*GSTAGE + b*GT_BYTES;
        const __nv_bfloat16* sp = srcs[b];
#pragma unroll
        for (int i = 0; i < 2; i++) {
            int g = i * 256 + tid;
            int row = g >> 2, c = g & 3;      // 128 rows x 4 16B-chunks
            cp16(dbase + row*80 + c*16, sp + (size_t)row*1024 + c*8);
        }
    }
    cp_commit();
}

__global__ __launch_bounds__(256) void gemm_ws_kernel(
    const __nv_bfloat16* __restrict__ Ah, const __nv_bfloat16* __restrict__ Al,
    const __nv_bfloat16* __restrict__ Bh, const __nv_bfloat16* __restrict__ Bl,
    __nv_bfloat16* __restrict__ outH, __nv_bfloat16* __restrict__ outL,
    float* __restrict__ outF, const float* __restrict__ bias,
    int ldc, int mode)
{
    extern __shared__ char sm[];
    const uint32_t sbase = s2u(sm);
    const int tid  = threadIdx.x;
    const int warp = tid >> 5;
    const int m0 = blockIdx.y << 7;
    const int n0 = blockIdx.x << 7;
    const int mw = (warp >> 2) * 64;   // 0 or 64
    const int nw = (warp & 3) * 32;    // 0..96

    wmma::fragment<wmma::accumulator, 16,16,16, float> acc[4][2];
#pragma unroll
    for (int i = 0; i < 4; i++)
#pragma unroll
        for (int j = 0; j < 2; j++) wmma::fill_fragment(acc[i][j], 0.0f);

    g_load_stage(sbase, 0, 0, m0, n0, tid, Ah, Al, Bh, Bl);
    g_load_stage(sbase, 1, 1, m0, n0, tid, Ah, Al, Bh, Bl);

    for (int kt = 0; kt < 32; kt++) {
        const int st = kt & 1;
        if (kt == 31) cp_wait0(); else cp_wait1();
        __syncthreads();

        const __nv_bfloat16* sAh = (const __nv_bfloat16*)(sm + st*GSTAGE);
        const __nv_bfloat16* sAl = sAh + 128*GLD;
        const __nv_bfloat16* sBh = sAl + 128*GLD;
        const __nv_bfloat16* sBl = sBh + 128*GLD;

#pragma unroll
        for (int kk = 0; kk < 2; kk++) {
            wmma::fragment<wmma::matrix_a, 16,16,16, __nv_bfloat16, wmma::row_major> ah[4], al[4];
#pragma unroll
            for (int i = 0; i < 4; i++) {
                wmma::load_matrix_sync(ah[i], sAh + (mw + i*16)*GLD + kk*16, GLD);
                wmma::load_matrix_sync(al[i], sAl + (mw + i*16)*GLD + kk*16, GLD);
            }
#pragma unroll
            for (int j = 0; j < 2; j++) {
                wmma::fragment<wmma::matrix_b, 16,16,16, __nv_bfloat16, wmma::col_major> bh, bl;
                wmma::load_matrix_sync(bh, sBh + (nw + j*16)*GLD + kk*16, GLD);
                wmma::load_matrix_sync(bl, sBl + (nw + j*16)*GLD + kk*16, GLD);
#pragma unroll
                for (int i = 0; i < 4; i++) {
                    wmma::mma_sync(acc[i][j], ah[i], bh, acc[i][j]);
                    wmma::mma_sync(acc[i][j], ah[i], bl, acc[i][j]);
                    wmma::mma_sync(acc[i][j], al[i], bh, acc[i][j]);
                }
            }
        }
        __syncthreads();
        if (kt + 2 < 32)
            g_load_stage(sbase, st, kt + 2, m0, n0, tid, Ah, Al, Bh, Bl);
    }

    // Epilogue: stage to f32 smem (reuses tile buffers), then write out.
    __syncthreads();
    float* Sst = (float*)sm;           // [128][ELD]
#pragma unroll
    for (int i = 0; i < 4; i++)
#pragma unroll
        for (int j = 0; j < 2; j++)
            wmma::store_matrix_sync(Sst + (mw + i*16)*ELD + nw + j*16,
                                    acc[i][j], ELD, wmma::mem_row_major);
    __syncthreads();

    const int row = tid >> 1;
    const int cb  = (tid & 1) << 6;    // 0 or 64
    if (mode == 0) {
        size_t ob = (size_t)(m0 + row) * ldc + n0 + cb;
#pragma unroll
        for (int c = 0; c < 64; c += 2)
            split_store2(Sst[row*ELD + cb + c], Sst[row*ELD + cb + c + 1],
                         outH + ob + c, outL + ob + c);
    } else {
        size_t ob = (size_t)(m0 + row) * ldc + n0 + cb;
#pragma unroll
        for (int c = 0; c < 64; c += 4) {
            float4 v;
            v.x = Sst[row*ELD + cb + c]     + bias[n0 + cb + c];
            v.y = Sst[row*ELD + cb + c + 1] + bias[n0 + cb + c + 1];
            v.z = Sst[row*ELD + cb + c + 2] + bias[n0 + cb + c + 2];
            v.w = Sst[row*ELD + cb + c + 3] + bias[n0 + cb + c + 3];
            *(float4*)(outF + ob + c) = v;
        }
    }
}

// ---------------------------------------------------------------------------
// Flash attention: wmma bf16-split compute, cp.async prefetched pre-split K/V.
// One block = (b,h) x 64 query rows, 256 threads = 8 warps.
// ---------------------------------------------------------------------------
#define ALDB 72   // bf16 smem ld (row bytes 144)
#define ALDS 68   // f32 smem ld
#define AQ_OFF   0
#define AKV_OFF  18432                       // 2*9216
#define AP_OFF   (AKV_OFF + 8*9216)          // 92160
#define AS_OFF   (AP_OFF + 2*9216)           // 110592
#define AO_OFF   (AS_OFF + 64*ALDS*4)        // 128000
#define AST_OFF  (AO_OFF + 64*ALDS*4)        // 145408
#define ATT_SMEM (AST_OFF + 3*256)           // 146176

__device__ __forceinline__ void attn_cp_kv(
    uint32_t sbase, int st, const __nv_bfloat16* qkvh, const __nv_bfloat16* qkvl,
    size_t rowbase /* (b*NT + jt*64)*3072 + h*64 */, int tid)
{
    int b = tid >> 6;           // 0:Kh 1:Kl 2:Vh 3:Vl
    int row = tid & 63;
    const __nv_bfloat16* src = ((b & 1) ? qkvl : qkvh)
        + rowbase + ((b >> 1) ? 2048 : 1024) + (size_t)row * 3072;
    uint32_t dst = sbase + AKV_OFF + (st*4 + b) * 9216 + row * 144;
#pragma unroll
    for (int c = 0; c < 8; c++) cp16(dst + c*16, src + c*8);
    cp_commit();
}

__global__ __launch_bounds__(256) void attn_wmma_kernel(
    const __nv_bfloat16* __restrict__ qkvh, const __nv_bfloat16* __restrict__ qkvl,
    __nv_bfloat16* __restrict__ atth, __nv_bfloat16* __restrict__ attl)
{
    extern __shared__ char smraw[];
    const uint32_t sbase = s2u(smraw);
    __nv_bfloat16* Qh = (__nv_bfloat16*)(smraw + AQ_OFF);
    __nv_bfloat16* Ql = (__nv_bfloat16*)(smraw + AQ_OFF + 9216);
    __nv_bfloat16* Ph = (__nv_bfloat16*)(smraw + AP_OFF);
    __nv_bfloat16* Pl = (__nv_bfloat16*)(smraw + AP_OFF + 9216);
    float* S   = (float*)(smraw + AS_OFF);
    float* O   = (float*)(smraw + AO_OFF);
    float* m_s = (float*)(smraw + AST_OFF);
    float* l_s = m_s + 64;
    float* c_s = l_s + 64;

    const int tid  = threadIdx.x;
    const int warp = tid >> 5;
    const int bh = blockIdx.y;
    const int qt = blockIdx.x;
    const int t0 = qt * 64;
    const int b_ = bh >> 4;
    const int h  = bh & 15;

    const int r  = tid >> 2;          // 0..63
    const int cq = (tid & 3) << 4;    // 0/16/32/48

    // Q load (cp.async, group 0)
    if (tid < 128) {
        int qb = tid >> 6;            // 0:Qh 1:Ql
        int row = tid & 63;
        const __nv_bfloat16* src = (qb ? qkvl : qkvh)
            + (size_t)(b_*NT + t0 + row) * 3072 + h*HD;
        uint32_t dst = sbase + AQ_OFF + qb * 9216 + row * 144;
#pragma unroll
        for (int c = 0; c < 8; c++) cp16(dst + c*16, src + c*8);
    }
    cp_commit();

    // K/V stage 0 (group 1)
    attn_cp_kv(sbase, 0, qkvh, qkvl, (size_t)(b_*NT) * 3072 + h*HD, tid);

    // init O and stats
#pragma unroll
    for (int u = 0; u < 4; u++) {
        int o = r*ALDS + cq + u*4;
        O[o] = 0.f; O[o+1] = 0.f; O[o+2] = 0.f; O[o+3] = 0.f;
    }
    if (tid < 64) { m_s[tid] = -1e30f; l_s[tid] = 0.f; }

    const int mw = warp >> 1;           // 0..3
    const int nb = (warp & 1) * 2;      // 0 or 2

    for (int jt = 0; jt <= qt; jt++) {
        int st = jt & 1;
        if (jt + 1 <= qt)
            attn_cp_kv(sbase, st ^ 1, qkvh, qkvl,
                       (size_t)(b_*NT + (jt+1)*64) * 3072 + h*HD, tid);
        if (jt + 1 <= qt) cp_wait1(); else cp_wait0();
        __syncthreads();

        __nv_bfloat16* Khs = (__nv_bfloat16*)(smraw + AKV_OFF + (st*4 + 0) * 9216);
        __nv_bfloat16* Kls = (__nv_bfloat16*)(smraw + AKV_OFF + (st*4 + 1) * 9216);
        __nv_bfloat16* Vhs = (__nv_bfloat16*)(smraw + AKV_OFF + (st*4 + 2) * 9216);
        __nv_bfloat16* Vls = (__nv_bfloat16*)(smraw + AKV_OFF + (st*4 + 3) * 9216);

        // S = Q K^T
        {
            wmma::fragment<wmma::accumulator,16,16,16,float> sacc[2];
            wmma::fill_fragment(sacc[0], 0.f);
            wmma::fill_fragment(sacc[1], 0.f);
#pragma unroll
            for (int kk = 0; kk < 4; kk++) {
                wmma::fragment<wmma::matrix_a,16,16,16,__nv_bfloat16,wmma::row_major> ah, al;
                wmma::load_matrix_sync(ah, Qh + (mw*16)*ALDB + kk*16, ALDB);
                wmma::load_matrix_sync(al, Ql + (mw*16)*ALDB + kk*16, ALDB);
#pragma unroll
                for (int j = 0; j < 2; j++) {
                    int n = nb + j;
                    wmma::fragment<wmma::matrix_b,16,16,16,__nv_bfloat16,wmma::col_major> bhf, blf;
                    wmma::load_matrix_sync(bhf, Khs + (n*16)*ALDB + kk*16, ALDB);
                    wmma::load_matrix_sync(blf, Kls + (n*16)*ALDB + kk*16, ALDB);
                    wmma::mma_sync(sacc[j], ah, bhf, sacc[j]);
                    wmma::mma_sync(sacc[j], ah, blf, sacc[j]);
                    wmma::mma_sync(sacc[j], al, bhf, sacc[j]);
                }
            }
            wmma::store_matrix_sync(S + (mw*16)*ALDS + nb*16,     sacc[0], ALDS, wmma::mem_row_major);
            wmma::store_matrix_sync(S + (mw*16)*ALDS + (nb+1)*16, sacc[1], ALDS, wmma::mem_row_major);
        }
        __syncthreads();

        // softmax step
        {
            const bool diag = (jt == qt);
            float v[16];
            float mx = -1e30f;
#pragma unroll
            for (int c = 0; c < 16; c++) {
                float s = S[r*ALDS + cq + c] * 8.0f;
                if (diag && (cq + c > r)) s = -1e30f;
                v[c] = s;
                mx = fmaxf(mx, s);
            }
            mx = fmaxf(mx, __shfl_xor_sync(0xffffffffu, mx, 1));
            mx = fmaxf(mx, __shfl_xor_sync(0xffffffffu, mx, 2));
            float mold = m_s[r];
            float mnew = fmaxf(mold, mx);
            float rsum = 0.f;
#pragma unroll
            for (int c = 0; c < 16; c += 2) {
                float p0 = __expf(v[c]   - mnew);
                float p1 = __expf(v[c+1] - mnew);
                rsum += p0 + p1;
                int o = r*ALDB + cq + c;
                split_store2(p0, p1, &Ph[o], &Pl[o]);
            }
            rsum += __shfl_xor_sync(0xffffffffu, rsum, 1);
            rsum += __shfl_xor_sync(0xffffffffu, rsum, 2);
            if ((tid & 3) == 0) {
                float corr = __expf(mold - mnew);
                c_s[r] = corr;
                m_s[r] = mnew;
                l_s[r] = l_s[r] * corr + rsum;
            }
        }
        __syncthreads();

        // Otile = P V  (into S staging)
        {
            wmma::fragment<wmma::accumulator,16,16,16,float> oacc[2];
            wmma::fill_fragment(oacc[0], 0.f);
            wmma::fill_fragment(oacc[1], 0.f);
#pragma unroll
            for (int kk = 0; kk < 4; kk++) {
                wmma::fragment<wmma::matrix_a,16,16,16,__nv_bfloat16,wmma::row_major> ah, al;
                wmma::load_matrix_sync(ah, Ph + (mw*16)*ALDB + kk*16, ALDB);
                wmma::load_matrix_sync(al, Pl + (mw*16)*ALDB + kk*16, ALDB);
#pragma unroll
                for (int j = 0; j < 2; j++) {
                    int n = nb + j;
                    wmma::fragment<wmma::matrix_b,16,16,16,__nv_bfloat16,wmma::row_major> bhf, blf;
                    wmma::load_matrix_sync(bhf, Vhs + (kk*16)*ALDB + n*16, ALDB);
                    wmma::load_matrix_sync(blf, Vls + (kk*16)*ALDB + n*16, ALDB);
                    wmma::mma_sync(oacc[j], ah, bhf, oacc[j]);
                    wmma::mma_sync(oacc[j], ah, blf, oacc[j]);
                    wmma::mma_sync(oacc[j], al, bhf, oacc[j]);
                }
            }
            wmma::store_matrix_sync(S + (mw*16)*ALDS + nb*16,     oacc[0], ALDS, wmma::mem_row_major);
            wmma::store_matrix_sync(S + (mw*16)*ALDS + (nb+1)*16, oacc[1], ALDS, wmma::mem_row_major);
        }
        __syncthreads();

        // merge running O
        {
            float corr = c_s[r];
#pragma unroll
            for (int u = 0; u < 16; u += 4) {
                int o = r*ALDS + cq + u;
                O[o]   = O[o]   * corr + S[o];
                O[o+1] = O[o+1] * corr + S[o+1];
                O[o+2] = O[o+2] * corr + S[o+2];
                O[o+3] = O[o+3] * corr + S[o+3];
            }
        }
    }

    // normalize + split-store to bf16 hi/lo att buffers
    {
        float inv = 1.0f / l_s[r];
        size_t ob = (size_t)(b_*NT + t0 + r) * NC + h*HD + cq;
#pragma unroll
        for (int u = 0; u < 16; u += 2) {
            float v0 = O[r*ALDS + cq + u]     * inv;
            float v1 = O[r*ALDS + cq + u + 1] * inv;
            split_store2(v0, v1, atth + ob + u, attl + ob + u);
        }
    }
}

// ---------------------------------------------------------------------------

extern "C" void kernel_launch(void* const* d_in, const int* in_sizes, int n_in,
                              void* d_out, int out_size)
{
    const float* x      = (const float*)d_in[0];
    const float* W_attn = (const float*)d_in[1];
    const float* W_proj = (const float*)d_in[2];
    const float* b_proj = (const float*)d_in[3];
    float* out = (float*)d_out;

    __nv_bfloat16 *xh, *xl, *wah, *wal, *wph, *wpl, *qkvh, *qkvl, *atth, *attl;
    cudaGetSymbolAddress((void**)&xh,   g_xh);
    cudaGetSymbolAddress((void**)&xl,   g_xl);
    cudaGetSymbolAddress((void**)&wah,  g_wah);
    cudaGetSymbolAddress((void**)&wal,  g_wal);
    cudaGetSymbolAddress((void**)&wph,  g_wph);
    cudaGetSymbolAddress((void**)&wpl,  g_wpl);
    cudaGetSymbolAddress((void**)&qkvh, g_qkvh);
    cudaGetSymbolAddress((void**)&qkvl, g_qkvl);
    cudaGetSymbolAddress((void**)&atth, g_atth);
    cudaGetSymbolAddress((void**)&attl, g_attl);

    cudaFuncSetAttribute(gemm_ws_kernel,
                         cudaFuncAttributeMaxDynamicSharedMemorySize, GEMM_SMEM);
    cudaFuncSetAttribute(attn_wmma_kernel,
                         cudaFuncAttributeMaxDynamicSharedMemorySize, ATT_SMEM);

    // pre-split inputs
    split_kernel<<<8192, 256>>>((const float4*)x,      xh,  xl,  2097152);
    split_kernel<<<3072, 256>>>((const float4*)W_attn, wah, wal, 786432);
    split_kernel<<<1024, 256>>>((const float4*)W_proj, wph, wpl, 262144);

    // QKV: [8192,1024] x [3072,1024]^T -> bf16 hi/lo [8192,3072]
    gemm_ws_kernel<<<dim3(24, 64), 256, GEMM_SMEM>>>(
        xh, xl, wah, wal, qkvh, qkvl, nullptr, nullptr, 3072, 0);

    // attention -> bf16 hi/lo [8192,1024]
    attn_wmma_kernel<<<dim3(32, 64), 256, ATT_SMEM>>>(qkvh, qkvl, atth, attl);

    // proj: [8192,1024] x [1024,1024]^T + bias -> f32 out
    gemm_ws_kernel<<<dim3(8, 64), 256, GEMM_SMEM>>>(
        atth, attl, wph, wpl, nullptr, nullptr, out, b_proj, 1024, 1);
}

// round 6
// speedup vs baseline: 2.4240x; 1.3707x over previous
#include <cuda_runtime.h>
#include <cuda_bf16.h>
#include <mma.h>
#include <math.h>
#include <cstdint>

using namespace nvcuda;

#define NB 4
#define NT 2048
#define NC 1024
#define NH 16
#define HD 64
#define MM (NB*NT)          // 8192

// ---------------- global scratch (device globals; no runtime alloc) --------
__device__ __nv_bfloat16 g_xh[(size_t)MM*NC],    g_xl[(size_t)MM*NC];
__device__ __nv_bfloat16 g_wah[(size_t)3*NC*NC], g_wal[(size_t)3*NC*NC];
__device__ __nv_bfloat16 g_wph[(size_t)NC*NC],   g_wpl[(size_t)NC*NC];
__device__ __nv_bfloat16 g_qkvh[(size_t)MM*3*NC],g_qkvl[(size_t)MM*3*NC];
__device__ __nv_bfloat16 g_atth[(size_t)MM*NC],  g_attl[(size_t)MM*NC];

// ---------------- helpers --------------------------------------------------
__device__ __forceinline__ uint32_t s2u(const void* p) {
    return (uint32_t)__cvta_generic_to_shared(p);
}
__device__ __forceinline__ void cp16(uint32_t dst, const void* src) {
    asm volatile("cp.async.cg.shared.global [%0], [%1], 16;" :: "r"(dst), "l"(src));
}
__device__ __forceinline__ void cp_commit() {
    asm volatile("cp.async.commit_group;" ::: "memory");
}
__device__ __forceinline__ void cp_wait1() {
    asm volatile("cp.async.wait_group 1;" ::: "memory");
}
__device__ __forceinline__ void cp_wait0() {
    asm volatile("cp.async.wait_group 0;" ::: "memory");
}
__device__ __forceinline__ void ldm4(uint32_t& r0, uint32_t& r1, uint32_t& r2,
                                     uint32_t& r3, uint32_t a) {
    asm volatile("ldmatrix.sync.aligned.m8n8.x4.shared.b16 {%0,%1,%2,%3}, [%4];"
                 : "=r"(r0), "=r"(r1), "=r"(r2), "=r"(r3) : "r"(a));
}
__device__ __forceinline__ void ldm4t(uint32_t& r0, uint32_t& r1, uint32_t& r2,
                                      uint32_t& r3, uint32_t a) {
    asm volatile("ldmatrix.sync.aligned.m8n8.x4.trans.shared.b16 {%0,%1,%2,%3}, [%4];"
                 : "=r"(r0), "=r"(r1), "=r"(r2), "=r"(r3) : "r"(a));
}
__device__ __forceinline__ void mma_bf16(float* c, uint32_t a0, uint32_t a1,
                                         uint32_t a2, uint32_t a3,
                                         uint32_t b0, uint32_t b1) {
    asm volatile("mma.sync.aligned.m16n8k16.row.col.f32.bf16.bf16.f32 "
                 "{%0,%1,%2,%3}, {%4,%5,%6,%7}, {%8,%9}, {%0,%1,%2,%3};"
                 : "+f"(c[0]), "+f"(c[1]), "+f"(c[2]), "+f"(c[3])
                 : "r"(a0), "r"(a1), "r"(a2), "r"(a3), "r"(b0), "r"(b1));
}

// Split fp32 -> bf16 hi + bf16 lo, packed pair stores
__device__ __forceinline__ void split_store2(float x, float y,
                                             __nv_bfloat16* hp, __nv_bfloat16* lp)
{
    __nv_bfloat16 hx = __float2bfloat16(x);
    __nv_bfloat16 hy = __float2bfloat16(y);
    float rx = x - __bfloat162float(hx);
    float ry = y - __bfloat162float(hy);
    *(__nv_bfloat162*)hp = __halves2bfloat162(hx, hy);
    *(__nv_bfloat162*)lp = __halves2bfloat162(__float2bfloat16(rx), __float2bfloat16(ry));
}
__device__ __forceinline__ void pack_hilo(float x, float y, uint32_t& h, uint32_t& l)
{
    __nv_bfloat16 hx = __float2bfloat16(x);
    __nv_bfloat16 hy = __float2bfloat16(y);
    float rx = x - __bfloat162float(hx);
    float ry = y - __bfloat162float(hy);
    __nv_bfloat162 hv = __halves2bfloat162(hx, hy);
    __nv_bfloat162 lv = __halves2bfloat162(__float2bfloat16(rx), __float2bfloat16(ry));
    h = *(uint32_t*)&hv;
    l = *(uint32_t*)&lv;
}

// ---------------- split kernel (f32 -> bf16 hi/lo) -------------------------
__global__ __launch_bounds__(256) void split_kernel(
    const float4* __restrict__ src, __nv_bfloat16* __restrict__ dh,
    __nv_bfloat16* __restrict__ dl, int n4)
{
    int i = blockIdx.x * 256 + threadIdx.x;
    if (i >= n4) return;
    float4 v = src[i];
    split_store2(v.x, v.y, dh + (size_t)i*4,     dl + (size_t)i*4);
    split_store2(v.z, v.w, dh + (size_t)i*4 + 2, dl + (size_t)i*4 + 2);
}

// ---------------------------------------------------------------------------
// wmma GEMM on pre-split bf16 (unchanged from R4): C = A * B^T, K=1024.
// ---------------------------------------------------------------------------
#define GLD 40
#define GT_BYTES (128*GLD*2)
#define GSTAGE   (4*GT_BYTES)
#define GEMM_SMEM (2*GSTAGE)
#define ELD 132

__device__ __forceinline__ void g_load_stage(
    uint32_t sbase, int st, int kt, int m0, int n0, int tid,
    const __nv_bfloat16* __restrict__ Ah, const __nv_bfloat16* __restrict__ Al,
    const __nv_bfloat16* __restrict__ Bh, const __nv_bfloat16* __restrict__ Bl)
{
    const __nv_bfloat16* srcs[4];
    srcs[0] = Ah + (size_t)m0 * 1024 + kt * 32;
    srcs[1] = Al + (size_t)m0 * 1024 + kt * 32;
    srcs[2] = Bh + (size_t)n0 * 1024 + kt * 32;
    srcs[3] = Bl + (size_t)n0 * 1024 + kt * 32;
#pragma unroll
    for (int b = 0; b < 4; b++) {
        uint32_t dbase = sbase + st*GSTAGE + b*GT_BYTES;
        const __nv_bfloat16* sp = srcs[b];
#pragma unroll
        for (int i = 0; i < 2; i++) {
            int g = i * 256 + tid;
            int row = g >> 2, c = g & 3;
            cp16(dbase + row*80 + c*16, sp + (size_t)row*1024 + c*8);
        }
    }
    cp_commit();
}

__global__ __launch_bounds__(256) void gemm_ws_kernel(
    const __nv_bfloat16* __restrict__ Ah, const __nv_bfloat16* __restrict__ Al,
    const __nv_bfloat16* __restrict__ Bh, const __nv_bfloat16* __restrict__ Bl,
    __nv_bfloat16* __restrict__ outH, __nv_bfloat16* __restrict__ outL,
    float* __restrict__ outF, const float* __restrict__ bias,
    int ldc, int mode)
{
    extern __shared__ char sm[];
    const uint32_t sbase = s2u(sm);
    const int tid  = threadIdx.x;
    const int warp = tid >> 5;
    const int m0 = blockIdx.y << 7;
    const int n0 = blockIdx.x << 7;
    const int mw = (warp >> 2) * 64;
    const int nw = (warp & 3) * 32;

    wmma::fragment<wmma::accumulator, 16,16,16, float> acc[4][2];
#pragma unroll
    for (int i = 0; i < 4; i++)
#pragma unroll
        for (int j = 0; j < 2; j++) wmma::fill_fragment(acc[i][j], 0.0f);

    g_load_stage(sbase, 0, 0, m0, n0, tid, Ah, Al, Bh, Bl);
    g_load_stage(sbase, 1, 1, m0, n0, tid, Ah, Al, Bh, Bl);

    for (int kt = 0; kt < 32; kt++) {
        const int st = kt & 1;
        if (kt == 31) cp_wait0(); else cp_wait1();
        __syncthreads();

        const __nv_bfloat16* sAh = (const __nv_bfloat16*)(sm + st*GSTAGE);
        const __nv_bfloat16* sAl = sAh + 128*GLD;
        const __nv_bfloat16* sBh = sAl + 128*GLD;
        const __nv_bfloat16* sBl = sBh + 128*GLD;

#pragma unroll
        for (int kk = 0; kk < 2; kk++) {
            wmma::fragment<wmma::matrix_a, 16,16,16, __nv_bfloat16, wmma::row_major> ah[4], al[4];
#pragma unroll
            for (int i = 0; i < 4; i++) {
                wmma::load_matrix_sync(ah[i], sAh + (mw + i*16)*GLD + kk*16, GLD);
                wmma::load_matrix_sync(al[i], sAl + (mw + i*16)*GLD + kk*16, GLD);
            }
#pragma unroll
            for (int j = 0; j < 2; j++) {
                wmma::fragment<wmma::matrix_b, 16,16,16, __nv_bfloat16, wmma::col_major> bh, bl;
                wmma::load_matrix_sync(bh, sBh + (nw + j*16)*GLD + kk*16, GLD);
                wmma::load_matrix_sync(bl, sBl + (nw + j*16)*GLD + kk*16, GLD);
#pragma unroll
                for (int i = 0; i < 4; i++) {
                    wmma::mma_sync(acc[i][j], ah[i], bh, acc[i][j]);
                    wmma::mma_sync(acc[i][j], ah[i], bl, acc[i][j]);
                    wmma::mma_sync(acc[i][j], al[i], bh, acc[i][j]);
                }
            }
        }
        __syncthreads();
        if (kt + 2 < 32)
            g_load_stage(sbase, st, kt + 2, m0, n0, tid, Ah, Al, Bh, Bl);
    }

    __syncthreads();
    float* Sst = (float*)sm;
#pragma unroll
    for (int i = 0; i < 4; i++)
#pragma unroll
        for (int j = 0; j < 2; j++)
            wmma::store_matrix_sync(Sst + (mw + i*16)*ELD + nw + j*16,
                                    acc[i][j], ELD, wmma::mem_row_major);
    __syncthreads();

    const int row = tid >> 1;
    const int cb  = (tid & 1) << 6;
    if (mode == 0) {
        size_t ob = (size_t)(m0 + row) * ldc + n0 + cb;
#pragma unroll
        for (int c = 0; c < 64; c += 2)
            split_store2(Sst[row*ELD + cb + c], Sst[row*ELD + cb + c + 1],
                         outH + ob + c, outL + ob + c);
    } else {
        size_t ob = (size_t)(m0 + row) * ldc + n0 + cb;
#pragma unroll
        for (int c = 0; c < 64; c += 4) {
            float4 v;
            v.x = Sst[row*ELD + cb + c]     + bias[n0 + cb + c];
            v.y = Sst[row*ELD + cb + c + 1] + bias[n0 + cb + c + 1];
            v.z = Sst[row*ELD + cb + c + 2] + bias[n0 + cb + c + 2];
            v.w = Sst[row*ELD + cb + c + 3] + bias[n0 + cb + c + 3];
            *(float4*)(outF + ob + c) = v;
        }
    }
}

// ---------------------------------------------------------------------------
// Register-resident flash attention (FA2-style, mma.sync m16n8k16).
// CTA = 128 q rows x one (b,h). 8 warps, warp = 16 q rows. kv tile = 64.
// smem: Q hi/lo 128x(64 pad 72) + 2 stages x {Kh,Kl,Vh,Vl} 64x72.
// ---------------------------------------------------------------------------
#define AROW 144                      // bytes per padded row (72 bf16)
#define AQ_BYTES   (128*AROW)         // 18432
#define AKV_BUF    (64*AROW)          // 9216
#define AKV_STAGE  (4*AKV_BUF)        // 36864
#define AKV_OFF    (2*AQ_BYTES)       // 36864
#define ATT_SMEM   (AKV_OFF + 2*AKV_STAGE)   // 110592

__device__ __forceinline__ void attn_cp_kv(
    uint32_t sbase, int st, const __nv_bfloat16* qkvh, const __nv_bfloat16* qkvl,
    size_t rowbase, int tid)
{
    int b = tid >> 6;           // 0:Kh 1:Kl 2:Vh 3:Vl
    int row = tid & 63;
    const __nv_bfloat16* src = ((b & 1) ? qkvl : qkvh)
        + rowbase + ((b >> 1) ? 2048 : 1024) + (size_t)row * 3072;
    uint32_t dst = sbase + AKV_OFF + st*AKV_STAGE + b*AKV_BUF + row*AROW;
#pragma unroll
    for (int c = 0; c < 8; c++) cp16(dst + c*16, src + c*8);
    cp_commit();
}

__global__ __launch_bounds__(256) void attn_fa2_kernel(
    const __nv_bfloat16* __restrict__ qkvh, const __nv_bfloat16* __restrict__ qkvl,
    __nv_bfloat16* __restrict__ atth, __nv_bfloat16* __restrict__ attl)
{
    extern __shared__ char smraw[];
    const uint32_t sbase = s2u(smraw);

    const int tid  = threadIdx.x;
    const int warp = tid >> 5;
    const int lid  = tid & 31;
    const int g    = lid >> 2;       // 0..7 (row in 8)
    const int qr   = lid & 3;        // col pair
    const int grp  = lid >> 3;       // ldmatrix address group
    const int rr   = lid & 7;

    const int qt = blockIdx.x;       // q tile (128 rows)
    const int bh = blockIdx.y;
    const int b_ = bh >> 4;
    const int h  = bh & 15;
    const int t0 = qt * 128;

    // ---- Q load (cp.async group 0) ----
    {
        int qb  = tid >> 7;          // 0:Qh 1:Ql
        int row = tid & 127;
        const __nv_bfloat16* src = (qb ? qkvl : qkvh)
            + (size_t)(b_*NT + t0 + row) * 3072 + h*HD;
        uint32_t dst = sbase + qb*AQ_BYTES + row*AROW;
#pragma unroll
        for (int c = 0; c < 8; c++) cp16(dst + c*16, src + c*8);
    }
    cp_commit();

    // ---- KV stage 0 (group 1) ----
    attn_cp_kv(sbase, 0, qkvh, qkvl, (size_t)(b_*NT) * 3072 + h*HD, tid);

    // wait Q (group count pending <= 1), then load Q fragments to registers
    cp_wait1();
    __syncthreads();

    uint32_t aqh[4][4], aql[4][4];
    {
        uint32_t rowoff = (16*warp + ((grp & 1) ? 8 : 0) + rr) * AROW
                        + ((grp >= 2) ? 16 : 0);
#pragma unroll
        for (int kk = 0; kk < 4; kk++) {
            ldm4(aqh[kk][0], aqh[kk][1], aqh[kk][2], aqh[kk][3],
                 sbase + rowoff + kk*32);
            ldm4(aql[kk][0], aql[kk][1], aql[kk][2], aql[kk][3],
                 sbase + AQ_BYTES + rowoff + kk*32);
        }
    }

    float O[8][4];
#pragma unroll
    for (int nt = 0; nt < 8; nt++) {
        O[nt][0] = 0.f; O[nt][1] = 0.f; O[nt][2] = 0.f; O[nt][3] = 0.f;
    }
    float m0 = -1e30f, m1 = -1e30f, l0 = 0.f, l1 = 0.f;

    const int i0 = t0 + 16*warp + g;     // global row (c0,c1)
    const int i1 = i0 + 8;               // global row (c2,c3)
    const int njt = 2*qt + 2;

    // ldmatrix address offsets (per-lane constants)
    const uint32_t k_rowsel = ((grp >= 2) ? 8 : 0) + rr;     // + n0
    const uint32_t k_colsel = ((grp & 1) ? 16 : 0);          // + kk*32 (bytes)
    const uint32_t v_rowsel = ((grp & 1) ? 8 : 0) + rr;      // + kk*16
    const uint32_t v_colsel = ((grp >= 2) ? 16 : 0);         // + n0*2 (bytes)

    for (int jt = 0; jt < njt; jt++) {
        const int st = jt & 1;
        if (jt + 1 < njt)
            attn_cp_kv(sbase, st ^ 1, qkvh, qkvl,
                       (size_t)(b_*NT + (jt+1)*64) * 3072 + h*HD, tid);
        if (jt + 1 < njt) cp_wait1(); else cp_wait0();
        __syncthreads();

        const uint32_t sK = sbase + AKV_OFF + st*AKV_STAGE;
        const uint32_t sKh = sK;
        const uint32_t sKl = sK + AKV_BUF;
        const uint32_t sVh = sK + 2*AKV_BUF;
        const uint32_t sVl = sK + 3*AKV_BUF;

        // ---- S = Q K^T (8 n-tiles of 8 kv cols) ----
        float S[8][4];
#pragma unroll
        for (int nt = 0; nt < 8; nt++) {
            S[nt][0] = 0.f; S[nt][1] = 0.f; S[nt][2] = 0.f; S[nt][3] = 0.f;
        }
#pragma unroll
        for (int kk = 0; kk < 4; kk++) {
#pragma unroll
            for (int np = 0; np < 4; np++) {
                uint32_t addr = (np*16 + k_rowsel)*AROW + kk*32 + k_colsel;
                uint32_t bh0, bh1, bh2, bh3, bl0, bl1, bl2, bl3;
                ldm4(bh0, bh1, bh2, bh3, sKh + addr);
                ldm4(bl0, bl1, bl2, bl3, sKl + addr);
                mma_bf16(S[2*np],   aqh[kk][0], aqh[kk][1], aqh[kk][2], aqh[kk][3], bh0, bh1);
                mma_bf16(S[2*np],   aqh[kk][0], aqh[kk][1], aqh[kk][2], aqh[kk][3], bl0, bl1);
                mma_bf16(S[2*np],   aql[kk][0], aql[kk][1], aql[kk][2], aql[kk][3], bh0, bh1);
                mma_bf16(S[2*np+1], aqh[kk][0], aqh[kk][1], aqh[kk][2], aqh[kk][3], bh2, bh3);
                mma_bf16(S[2*np+1], aqh[kk][0], aqh[kk][1], aqh[kk][2], aqh[kk][3], bl2, bl3);
                mma_bf16(S[2*np+1], aql[kk][0], aql[kk][1], aql[kk][2], aql[kk][3], bh2, bh3);
            }
        }

        // ---- scale + causal mask ----
        const bool need_mask = (jt >= 2*qt);
#pragma unroll
        for (int nt = 0; nt < 8; nt++) {
            int jb = jt*64 + nt*8 + qr*2;
            float s0 = S[nt][0] * 8.f, s1 = S[nt][1] * 8.f;
            float s2 = S[nt][2] * 8.f, s3 = S[nt][3] * 8.f;
            if (need_mask) {
                if (jb     > i0) s0 = -1e30f;
                if (jb + 1 > i0) s1 = -1e30f;
                if (jb     > i1) s2 = -1e30f;
                if (jb + 1 > i1) s3 = -1e30f;
            }
            S[nt][0] = s0; S[nt][1] = s1; S[nt][2] = s2; S[nt][3] = s3;
        }

        // ---- online softmax (register + quad shfl) ----
        float mx0 = -1e30f, mx1 = -1e30f;
#pragma unroll
        for (int nt = 0; nt < 8; nt++) {
            mx0 = fmaxf(mx0, fmaxf(S[nt][0], S[nt][1]));
            mx1 = fmaxf(mx1, fmaxf(S[nt][2], S[nt][3]));
        }
        mx0 = fmaxf(mx0, __shfl_xor_sync(0xffffffffu, mx0, 1));
        mx0 = fmaxf(mx0, __shfl_xor_sync(0xffffffffu, mx0, 2));
        mx1 = fmaxf(mx1, __shfl_xor_sync(0xffffffffu, mx1, 1));
        mx1 = fmaxf(mx1, __shfl_xor_sync(0xffffffffu, mx1, 2));

        float mn0 = fmaxf(m0, mx0), mn1 = fmaxf(m1, mx1);
        float corr0 = __expf(m0 - mn0), corr1 = __expf(m1 - mn1);
        m0 = mn0; m1 = mn1;

        float sum0 = 0.f, sum1 = 0.f;
#pragma unroll
        for (int nt = 0; nt < 8; nt++) {
            float p0 = __expf(S[nt][0] - mn0);
            float p1 = __expf(S[nt][1] - mn0);
            float p2 = __expf(S[nt][2] - mn1);
            float p3 = __expf(S[nt][3] - mn1);
            sum0 += p0 + p1; sum1 += p2 + p3;
            S[nt][0] = p0; S[nt][1] = p1; S[nt][2] = p2; S[nt][3] = p3;
        }
        sum0 += __shfl_xor_sync(0xffffffffu, sum0, 1);
        sum0 += __shfl_xor_sync(0xffffffffu, sum0, 2);
        sum1 += __shfl_xor_sync(0xffffffffu, sum1, 1);
        sum1 += __shfl_xor_sync(0xffffffffu, sum1, 2);
        l0 = l0 * corr0 + sum0;
        l1 = l1 * corr1 + sum1;

        // rescale O
#pragma unroll
        for (int nt = 0; nt < 8; nt++) {
            O[nt][0] *= corr0; O[nt][1] *= corr0;
            O[nt][2] *= corr1; O[nt][3] *= corr1;
        }

        // ---- O += P V ----
#pragma unroll
        for (int kk = 0; kk < 4; kk++) {
            uint32_t ah0, ah1, ah2, ah3, al0, al1, al2, al3;
            pack_hilo(S[2*kk][0],   S[2*kk][1],   ah0, al0);
            pack_hilo(S[2*kk][2],   S[2*kk][3],   ah1, al1);
            pack_hilo(S[2*kk+1][0], S[2*kk+1][1], ah2, al2);
            pack_hilo(S[2*kk+1][2], S[2*kk+1][3], ah3, al3);
#pragma unroll
            for (int np = 0; np < 4; np++) {
                uint32_t addr = (kk*16 + v_rowsel)*AROW + np*32 + v_colsel;
                uint32_t bh0, bh1, bh2, bh3, bl0, bl1, bl2, bl3;
                ldm4t(bh0, bh1, bh2, bh3, sVh + addr);
                ldm4t(bl0, bl1, bl2, bl3, sVl + addr);
                mma_bf16(O[2*np],   ah0, ah1, ah2, ah3, bh0, bh1);
                mma_bf16(O[2*np],   ah0, ah1, ah2, ah3, bl0, bl1);
                mma_bf16(O[2*np],   al0, al1, al2, al3, bh0, bh1);
                mma_bf16(O[2*np+1], ah0, ah1, ah2, ah3, bh2, bh3);
                mma_bf16(O[2*np+1], ah0, ah1, ah2, ah3, bl2, bl3);
                mma_bf16(O[2*np+1], al0, al1, al2, al3, bh2, bh3);
            }
        }
        __syncthreads();   // all warps done reading stage before next prefetch overwrites
    }

    // ---- normalize + split-store out ----
    float inv0 = 1.f / l0, inv1 = 1.f / l1;
    size_t r0 = (size_t)(b_*NT + i0) * NC + h*HD + qr*2;
    size_t r1 = (size_t)(b_*NT + i1) * NC + h*HD + qr*2;
#pragma unroll
    for (int nt = 0; nt < 8; nt++) {
        split_store2(O[nt][0]*inv0, O[nt][1]*inv0, atth + r0 + nt*8, attl + r0 + nt*8);
        split_store2(O[nt][2]*inv1, O[nt][3]*inv1, atth + r1 + nt*8, attl + r1 + nt*8);
    }
}

// ---------------------------------------------------------------------------

extern "C" void kernel_launch(void* const* d_in, const int* in_sizes, int n_in,
                              void* d_out, int out_size)
{
    const float* x      = (const float*)d_in[0];
    const float* W_attn = (const float*)d_in[1];
    const float* W_proj = (const float*)d_in[2];
    const float* b_proj = (const float*)d_in[3];
    float* out = (float*)d_out;

    __nv_bfloat16 *xh, *xl, *wah, *wal, *wph, *wpl, *qkvh, *qkvl, *atth, *attl;
    cudaGetSymbolAddress((void**)&xh,   g_xh);
    cudaGetSymbolAddress((void**)&xl,   g_xl);
    cudaGetSymbolAddress((void**)&wah,  g_wah);
    cudaGetSymbolAddress((void**)&wal,  g_wal);
    cudaGetSymbolAddress((void**)&wph,  g_wph);
    cudaGetSymbolAddress((void**)&wpl,  g_wpl);
    cudaGetSymbolAddress((void**)&qkvh, g_qkvh);
    cudaGetSymbolAddress((void**)&qkvl, g_qkvl);
    cudaGetSymbolAddress((void**)&atth, g_atth);
    cudaGetSymbolAddress((void**)&attl, g_attl);

    cudaFuncSetAttribute(gemm_ws_kernel,
                         cudaFuncAttributeMaxDynamicSharedMemorySize, GEMM_SMEM);
    cudaFuncSetAttribute(attn_fa2_kernel,
                         cudaFuncAttributeMaxDynamicSharedMemorySize, ATT_SMEM);

    split_kernel<<<8192, 256>>>((const float4*)x,      xh,  xl,  2097152);
    split_kernel<<<3072, 256>>>((const float4*)W_attn, wah, wal, 786432);
    split_kernel<<<1024, 256>>>((const float4*)W_proj, wph, wpl, 262144);

    gemm_ws_kernel<<<dim3(24, 64), 256, GEMM_SMEM>>>(
        xh, xl, wah, wal, qkvh, qkvl, nullptr, nullptr, 3072, 0);

    attn_fa2_kernel<<<dim3(16, 64), 256, ATT_SMEM>>>(qkvh, qkvl, atth, attl);

    gemm_ws_kernel<<<dim3(8, 64), 256, GEMM_SMEM>>>(
        atth, attl, wph, wpl, nullptr, nullptr, out, b_proj, 1024, 1);
}

// round 7
// speedup vs baseline: 2.8134x; 1.1607x over previous
#include <cuda_runtime.h>
#include <cuda_bf16.h>
#include <math.h>
#include <cstdint>

#define NB 4
#define NT 2048
#define NC 1024
#define NH 16
#define HD 64
#define MM (NB*NT)          // 8192

// ---------------- global scratch (device globals; no runtime alloc) --------
__device__ __nv_bfloat16 g_xh[(size_t)MM*NC],    g_xl[(size_t)MM*NC];
__device__ __nv_bfloat16 g_wah[(size_t)3*NC*NC], g_wal[(size_t)3*NC*NC];
__device__ __nv_bfloat16 g_wph[(size_t)NC*NC],   g_wpl[(size_t)NC*NC];
__device__ __nv_bfloat16 g_qkvh[(size_t)MM*3*NC],g_qkvl[(size_t)MM*3*NC];
__device__ __nv_bfloat16 g_atth[(size_t)MM*NC],  g_attl[(size_t)MM*NC];

// ---------------- helpers --------------------------------------------------
__device__ __forceinline__ uint32_t s2u(const void* p) {
    return (uint32_t)__cvta_generic_to_shared(p);
}
__device__ __forceinline__ void cp16(uint32_t dst, const void* src) {
    asm volatile("cp.async.cg.shared.global [%0], [%1], 16;" :: "r"(dst), "l"(src));
}
__device__ __forceinline__ void cp_commit() {
    asm volatile("cp.async.commit_group;" ::: "memory");
}
__device__ __forceinline__ void cp_wait1() {
    asm volatile("cp.async.wait_group 1;" ::: "memory");
}
__device__ __forceinline__ void cp_wait0() {
    asm volatile("cp.async.wait_group 0;" ::: "memory");
}
__device__ __forceinline__ void ldm4(uint32_t& r0, uint32_t& r1, uint32_t& r2,
                                     uint32_t& r3, uint32_t a) {
    asm volatile("ldmatrix.sync.aligned.m8n8.x4.shared.b16 {%0,%1,%2,%3}, [%4];"
                 : "=r"(r0), "=r"(r1), "=r"(r2), "=r"(r3) : "r"(a));
}
__device__ __forceinline__ void ldm4t(uint32_t& r0, uint32_t& r1, uint32_t& r2,
                                      uint32_t& r3, uint32_t a) {
    asm volatile("ldmatrix.sync.aligned.m8n8.x4.trans.shared.b16 {%0,%1,%2,%3}, [%4];"
                 : "=r"(r0), "=r"(r1), "=r"(r2), "=r"(r3) : "r"(a));
}
__device__ __forceinline__ void mma_bf16(float* c, uint32_t a0, uint32_t a1,
                                         uint32_t a2, uint32_t a3,
                                         uint32_t b0, uint32_t b1) {
    asm volatile("mma.sync.aligned.m16n8k16.row.col.f32.bf16.bf16.f32 "
                 "{%0,%1,%2,%3}, {%4,%5,%6,%7}, {%8,%9}, {%0,%1,%2,%3};"
                 : "+f"(c[0]), "+f"(c[1]), "+f"(c[2]), "+f"(c[3])
                 : "r"(a0), "r"(a1), "r"(a2), "r"(a3), "r"(b0), "r"(b1));
}

// Split fp32 -> bf16 hi + bf16 lo, packed pair stores
__device__ __forceinline__ void split_store2(float x, float y,
                                             __nv_bfloat16* hp, __nv_bfloat16* lp)
{
    __nv_bfloat16 hx = __float2bfloat16(x);
    __nv_bfloat16 hy = __float2bfloat16(y);
    float rx = x - __bfloat162float(hx);
    float ry = y - __bfloat162float(hy);
    *(__nv_bfloat162*)hp = __halves2bfloat162(hx, hy);
    *(__nv_bfloat162*)lp = __halves2bfloat162(__float2bfloat16(rx), __float2bfloat16(ry));
}
__device__ __forceinline__ void pack_hilo(float x, float y, uint32_t& h, uint32_t& l)
{
    __nv_bfloat16 hx = __float2bfloat16(x);
    __nv_bfloat16 hy = __float2bfloat16(y);
    float rx = x - __bfloat162float(hx);
    float ry = y - __bfloat162float(hy);
    __nv_bfloat162 hv = __halves2bfloat162(hx, hy);
    __nv_bfloat162 lv = __halves2bfloat162(__float2bfloat16(rx), __float2bfloat16(ry));
    h = *(uint32_t*)&hv;
    l = *(uint32_t*)&lv;
}

// ---------------- split kernel (f32 -> bf16 hi/lo) -------------------------
__global__ __launch_bounds__(256) void split_kernel(
    const float4* __restrict__ src, __nv_bfloat16* __restrict__ dh,
    __nv_bfloat16* __restrict__ dl, int n4)
{
    int i = blockIdx.x * 256 + threadIdx.x;
    if (i >= n4) return;
    float4 v = src[i];
    split_store2(v.x, v.y, dh + (size_t)i*4,     dl + (size_t)i*4);
    split_store2(v.z, v.w, dh + (size_t)i*4 + 2, dl + (size_t)i*4 + 2);
}

// ---------------------------------------------------------------------------
// mma.sync GEMM on pre-split bf16: C[m][n] = sum_k A[m][k]*B[n][k], K=1024.
// CTA 128x256, 8 warps (warp = 64x64), BK=32, 3-stage cp.async pipeline.
// Tile rows padded to 80 B (conflict-free for ldmatrix, stride 20 banks).
// ---------------------------------------------------------------------------
#define GABUF 10240                 // 128 rows * 80 B
#define GBBUF 20480                 // 256 rows * 80 B
#define GSTG  61440                 // Ah + Al + Bh + Bl
#define GEMM_SMEM (3*GSTG)          // 184320 (also reused as f32 staging)
#define ELD 260                     // f32 staging leading dim (256 + 4 pad)

__device__ __forceinline__ void g_load_stage(
    uint32_t sbase, int st, int kt, int m0, int n0, int tid,
    const __nv_bfloat16* __restrict__ Ah, const __nv_bfloat16* __restrict__ Al,
    const __nv_bfloat16* __restrict__ Bh, const __nv_bfloat16* __restrict__ Bl)
{
    const int koff = kt * 32;
    const uint32_t dbase = sbase + st * GSTG;
#pragma unroll
    for (int i = 0; i < 2; i++) {
        int gidx = i * 256 + tid;
        int row = gidx >> 2, c = gidx & 3;
        uint32_t doff = row * 80 + c * 16;
        size_t soff = (size_t)(m0 + row) * 1024 + koff + c * 8;
        cp16(dbase + doff,         Ah + soff);
        cp16(dbase + GABUF + doff, Al + soff);
    }
#pragma unroll
    for (int i = 0; i < 4; i++) {
        int gidx = i * 256 + tid;
        int row = gidx >> 2, c = gidx & 3;
        uint32_t doff = row * 80 + c * 16;
        size_t soff = (size_t)(n0 + row) * 1024 + koff + c * 8;
        cp16(dbase + 2*GABUF + doff,         Bh + soff);
        cp16(dbase + 2*GABUF + GBBUF + doff, Bl + soff);
    }
    cp_commit();
}

__global__ __launch_bounds__(256, 1) void gemm_mma_kernel(
    const __nv_bfloat16* __restrict__ Ah, const __nv_bfloat16* __restrict__ Al,
    const __nv_bfloat16* __restrict__ Bh, const __nv_bfloat16* __restrict__ Bl,
    __nv_bfloat16* __restrict__ outH, __nv_bfloat16* __restrict__ outL,
    float* __restrict__ outF, const float* __restrict__ bias,
    int ldc, int mode)
{
    extern __shared__ char sm[];
    const uint32_t sbase = s2u(sm);
    const int tid  = threadIdx.x;
    const int warp = tid >> 5;
    const int lid  = tid & 31;
    const int g    = lid >> 2;
    const int qr   = lid & 3;
    const int grp  = lid >> 3;
    const int rr   = lid & 7;

    const int m0 = blockIdx.y << 7;
    const int n0 = blockIdx.x << 8;
    const int mw = (warp >> 2) * 64;   // 0 or 64
    const int nw = (warp & 3) * 64;    // 0..192

    // per-lane ldmatrix selectors (validated layout from attention kernel)
    const uint32_t a_rowsel = ((grp & 1) ? 8 : 0) + rr;
    const uint32_t a_colsel = (grp >= 2) ? 16 : 0;
    const uint32_t b_rowsel = ((grp >= 2) ? 8 : 0) + rr;
    const uint32_t b_colsel = (grp & 1) ? 16 : 0;

    float acc[4][8][4];
#pragma unroll
    for (int mt = 0; mt < 4; mt++)
#pragma unroll
        for (int nt = 0; nt < 8; nt++) {
            acc[mt][nt][0] = 0.f; acc[mt][nt][1] = 0.f;
            acc[mt][nt][2] = 0.f; acc[mt][nt][3] = 0.f;
        }

    g_load_stage(sbase, 0, 0, m0, n0, tid, Ah, Al, Bh, Bl);
    g_load_stage(sbase, 1, 1, m0, n0, tid, Ah, Al, Bh, Bl);

    int stidx = 0;
    for (int kt = 0; kt < 32; kt++) {
        cp_wait1();
        __syncthreads();

        // prefetch stage kt+2 into buffer (kt+2)%3 (free: read at kt-1)
        if (kt + 2 < 32) {
            int st2 = stidx + 2; if (st2 >= 3) st2 -= 3;
            g_load_stage(sbase, st2, kt + 2, m0, n0, tid, Ah, Al, Bh, Bl);
        } else {
            cp_commit();
        }

        const uint32_t sb  = sbase + stidx * GSTG;
        const uint32_t sAh = sb;
        const uint32_t sAl = sb + GABUF;
        const uint32_t sBh = sb + 2*GABUF;
        const uint32_t sBl = sb + 2*GABUF + GBBUF;

#pragma unroll
        for (int kk = 0; kk < 2; kk++) {
            uint32_t ah[4][4], al[4][4];
#pragma unroll
            for (int mt = 0; mt < 4; mt++) {
                uint32_t ra = (mw + mt*16 + a_rowsel) * 80 + kk*32 + a_colsel;
                ldm4(ah[mt][0], ah[mt][1], ah[mt][2], ah[mt][3], sAh + ra);
                ldm4(al[mt][0], al[mt][1], al[mt][2], al[mt][3], sAl + ra);
            }
#pragma unroll
            for (int nc = 0; nc < 4; nc++) {
                uint32_t rb = (nw + nc*16 + b_rowsel) * 80 + kk*32 + b_colsel;
                uint32_t bh0, bh1, bh2, bh3, bl0, bl1, bl2, bl3;
                ldm4(bh0, bh1, bh2, bh3, sBh + rb);
                ldm4(bl0, bl1, bl2, bl3, sBl + rb);
#pragma unroll
                for (int mt = 0; mt < 4; mt++) {
                    mma_bf16(acc[mt][2*nc],   ah[mt][0], ah[mt][1], ah[mt][2], ah[mt][3], bh0, bh1);
                    mma_bf16(acc[mt][2*nc+1], ah[mt][0], ah[mt][1], ah[mt][2], ah[mt][3], bh2, bh3);
                }
#pragma unroll
                for (int mt = 0; mt < 4; mt++) {
                    mma_bf16(acc[mt][2*nc],   ah[mt][0], ah[mt][1], ah[mt][2], ah[mt][3], bl0, bl1);
                    mma_bf16(acc[mt][2*nc+1], ah[mt][0], ah[mt][1], ah[mt][2], ah[mt][3], bl2, bl3);
                }
#pragma unroll
                for (int mt = 0; mt < 4; mt++) {
                    mma_bf16(acc[mt][2*nc],   al[mt][0], al[mt][1], al[mt][2], al[mt][3], bh0, bh1);
                    mma_bf16(acc[mt][2*nc+1], al[mt][0], al[mt][1], al[mt][2], al[mt][3], bh2, bh3);
                }
            }
        }
        if (++stidx == 3) stidx = 0;
    }

    // ---------------- epilogue: stage f32 in smem, write coalesced ---------
    cp_wait0();
    __syncthreads();
    float* Sst = (float*)sm;    // [128][ELD]
#pragma unroll
    for (int mt = 0; mt < 4; mt++) {
        int row = mw + mt*16 + g;
#pragma unroll
        for (int nt = 0; nt < 8; nt++) {
            int col = nw + nt*8 + qr*2;
            *(float2*)&Sst[row*ELD + col]       = make_float2(acc[mt][nt][0], acc[mt][nt][1]);
            *(float2*)&Sst[(row+8)*ELD + col]   = make_float2(acc[mt][nt][2], acc[mt][nt][3]);
        }
    }
    __syncthreads();

    if (mode == 0) {
#pragma unroll 1
        for (int r = 0; r < 16; r++) {
            int row = warp*16 + r;
            size_t ob = (size_t)(m0 + row) * ldc + n0;
#pragma unroll
            for (int blk = 0; blk < 4; blk++) {
                int c = blk*64 + lid*2;
                float2 v = *(float2*)&Sst[row*ELD + c];
                split_store2(v.x, v.y, outH + ob + c, outL + ob + c);
            }
        }
    } else {
#pragma unroll 1
        for (int r = 0; r < 16; r++) {
            int row = warp*16 + r;
            size_t ob = (size_t)(m0 + row) * ldc + n0;
#pragma unroll
            for (int blk = 0; blk < 2; blk++) {
                int c = blk*128 + lid*4;
                float4 v = *(float4*)&Sst[row*ELD + c];
                v.x += bias[n0 + c];     v.y += bias[n0 + c + 1];
                v.z += bias[n0 + c + 2]; v.w += bias[n0 + c + 3];
                *(float4*)(outF + ob + c) = v;
            }
        }
    }
}

// ---------------------------------------------------------------------------
// Register-resident flash attention (unchanged from R5).
// ---------------------------------------------------------------------------
#define AROW 144
#define AQ_BYTES   (128*AROW)
#define AKV_BUF    (64*AROW)
#define AKV_STAGE  (4*AKV_BUF)
#define AKV_OFF    (2*AQ_BYTES)
#define ATT_SMEM   (AKV_OFF + 2*AKV_STAGE)

__device__ __forceinline__ void attn_cp_kv(
    uint32_t sbase, int st, const __nv_bfloat16* qkvh, const __nv_bfloat16* qkvl,
    size_t rowbase, int tid)
{
    int b = tid >> 6;
    int row = tid & 63;
    const __nv_bfloat16* src = ((b & 1) ? qkvl : qkvh)
        + rowbase + ((b >> 1) ? 2048 : 1024) + (size_t)row * 3072;
    uint32_t dst = sbase + AKV_OFF + st*AKV_STAGE + b*AKV_BUF + row*AROW;
#pragma unroll
    for (int c = 0; c < 8; c++) cp16(dst + c*16, src + c*8);
    cp_commit();
}

__global__ __launch_bounds__(256) void attn_fa2_kernel(
    const __nv_bfloat16* __restrict__ qkvh, const __nv_bfloat16* __restrict__ qkvl,
    __nv_bfloat16* __restrict__ atth, __nv_bfloat16* __restrict__ attl)
{
    extern __shared__ char smraw[];
    const uint32_t sbase = s2u(smraw);

    const int tid  = threadIdx.x;
    const int warp = tid >> 5;
    const int lid  = tid & 31;
    const int g    = lid >> 2;
    const int qr   = lid & 3;
    const int grp  = lid >> 3;
    const int rr   = lid & 7;

    const int qt = blockIdx.x;
    const int bh = blockIdx.y;
    const int b_ = bh >> 4;
    const int h  = bh & 15;
    const int t0 = qt * 128;

    {
        int qb  = tid >> 7;
        int row = tid & 127;
        const __nv_bfloat16* src = (qb ? qkvl : qkvh)
            + (size_t)(b_*NT + t0 + row) * 3072 + h*HD;
        uint32_t dst = sbase + qb*AQ_BYTES + row*AROW;
#pragma unroll
        for (int c = 0; c < 8; c++) cp16(dst + c*16, src + c*8);
    }
    cp_commit();

    attn_cp_kv(sbase, 0, qkvh, qkvl, (size_t)(b_*NT) * 3072 + h*HD, tid);

    cp_wait1();
    __syncthreads();

    uint32_t aqh[4][4], aql[4][4];
    {
        uint32_t rowoff = (16*warp + ((grp & 1) ? 8 : 0) + rr) * AROW
                        + ((grp >= 2) ? 16 : 0);
#pragma unroll
        for (int kk = 0; kk < 4; kk++) {
            ldm4(aqh[kk][0], aqh[kk][1], aqh[kk][2], aqh[kk][3],
                 sbase + rowoff + kk*32);
            ldm4(aql[kk][0], aql[kk][1], aql[kk][2], aql[kk][3],
                 sbase + AQ_BYTES + rowoff + kk*32);
        }
    }

    float O[8][4];
#pragma unroll
    for (int nt = 0; nt < 8; nt++) {
        O[nt][0] = 0.f; O[nt][1] = 0.f; O[nt][2] = 0.f; O[nt][3] = 0.f;
    }
    float m0 = -1e30f, m1 = -1e30f, l0 = 0.f, l1 = 0.f;

    const int i0 = t0 + 16*warp + g;
    const int i1 = i0 + 8;
    const int njt = 2*qt + 2;

    const uint32_t k_rowsel = ((grp >= 2) ? 8 : 0) + rr;
    const uint32_t k_colsel = ((grp & 1) ? 16 : 0);
    const uint32_t v_rowsel = ((grp & 1) ? 8 : 0) + rr;
    const uint32_t v_colsel = ((grp >= 2) ? 16 : 0);

    for (int jt = 0; jt < njt; jt++) {
        const int st = jt & 1;
        if (jt + 1 < njt)
            attn_cp_kv(sbase, st ^ 1, qkvh, qkvl,
                       (size_t)(b_*NT + (jt+1)*64) * 3072 + h*HD, tid);
        if (jt + 1 < njt) cp_wait1(); else cp_wait0();
        __syncthreads();

        const uint32_t sK = sbase + AKV_OFF + st*AKV_STAGE;
        const uint32_t sKh = sK;
        const uint32_t sKl = sK + AKV_BUF;
        const uint32_t sVh = sK + 2*AKV_BUF;
        const uint32_t sVl = sK + 3*AKV_BUF;

        float S[8][4];
#pragma unroll
        for (int nt = 0; nt < 8; nt++) {
            S[nt][0] = 0.f; S[nt][1] = 0.f; S[nt][2] = 0.f; S[nt][3] = 0.f;
        }
#pragma unroll
        for (int kk = 0; kk < 4; kk++) {
#pragma unroll
            for (int np = 0; np < 4; np++) {
                uint32_t addr = (np*16 + k_rowsel)*AROW + kk*32 + k_colsel;
                uint32_t bh0, bh1, bh2, bh3, bl0, bl1, bl2, bl3;
                ldm4(bh0, bh1, bh2, bh3, sKh + addr);
                ldm4(bl0, bl1, bl2, bl3, sKl + addr);
                mma_bf16(S[2*np],   aqh[kk][0], aqh[kk][1], aqh[kk][2], aqh[kk][3], bh0, bh1);
                mma_bf16(S[2*np],   aqh[kk][0], aqh[kk][1], aqh[kk][2], aqh[kk][3], bl0, bl1);
                mma_bf16(S[2*np],   aql[kk][0], aql[kk][1], aql[kk][2], aql[kk][3], bh0, bh1);
                mma_bf16(S[2*np+1], aqh[kk][0], aqh[kk][1], aqh[kk][2], aqh[kk][3], bh2, bh3);
                mma_bf16(S[2*np+1], aqh[kk][0], aqh[kk][1], aqh[kk][2], aqh[kk][3], bl2, bl3);
                mma_bf16(S[2*np+1], aql[kk][0], aql[kk][1], aql[kk][2], aql[kk][3], bh2, bh3);
            }
        }

        const bool need_mask = (jt >= 2*qt);
#pragma unroll
        for (int nt = 0; nt < 8; nt++) {
            int jb = jt*64 + nt*8 + qr*2;
            float s0 = S[nt][0] * 8.f, s1 = S[nt][1] * 8.f;
            float s2 = S[nt][2] * 8.f, s3 = S[nt][3] * 8.f;
            if (need_mask) {
                if (jb     > i0) s0 = -1e30f;
                if (jb + 1 > i0) s1 = -1e30f;
                if (jb     > i1) s2 = -1e30f;
                if (jb + 1 > i1) s3 = -1e30f;
            }
            S[nt][0] = s0; S[nt][1] = s1; S[nt][2] = s2; S[nt][3] = s3;
        }

        float mx0 = -1e30f, mx1 = -1e30f;
#pragma unroll
        for (int nt = 0; nt < 8; nt++) {
            mx0 = fmaxf(mx0, fmaxf(S[nt][0], S[nt][1]));
            mx1 = fmaxf(mx1, fmaxf(S[nt][2], S[nt][3]));
        }
        mx0 = fmaxf(mx0, __shfl_xor_sync(0xffffffffu, mx0, 1));
        mx0 = fmaxf(mx0, __shfl_xor_sync(0xffffffffu, mx0, 2));
        mx1 = fmaxf(mx1, __shfl_xor_sync(0xffffffffu, mx1, 1));
        mx1 = fmaxf(mx1, __shfl_xor_sync(0xffffffffu, mx1, 2));

        float mn0 = fmaxf(m0, mx0), mn1 = fmaxf(m1, mx1);
        float corr0 = __expf(m0 - mn0), corr1 = __expf(m1 - mn1);
        m0 = mn0; m1 = mn1;

        float sum0 = 0.f, sum1 = 0.f;
#pragma unroll
        for (int nt = 0; nt < 8; nt++) {
            float p0 = __expf(S[nt][0] - mn0);
            float p1 = __expf(S[nt][1] - mn0);
            float p2 = __expf(S[nt][2] - mn1);
            float p3 = __expf(S[nt][3] - mn1);
            sum0 += p0 + p1; sum1 += p2 + p3;
            S[nt][0] = p0; S[nt][1] = p1; S[nt][2] = p2; S[nt][3] = p3;
        }
        sum0 += __shfl_xor_sync(0xffffffffu, sum0, 1);
        sum0 += __shfl_xor_sync(0xffffffffu, sum0, 2);
        sum1 += __shfl_xor_sync(0xffffffffu, sum1, 1);
        sum1 += __shfl_xor_sync(0xffffffffu, sum1, 2);
        l0 = l0 * corr0 + sum0;
        l1 = l1 * corr1 + sum1;

#pragma unroll
        for (int nt = 0; nt < 8; nt++) {
            O[nt][0] *= corr0; O[nt][1] *= corr0;
            O[nt][2] *= corr1; O[nt][3] *= corr1;
        }

#pragma unroll
        for (int kk = 0; kk < 4; kk++) {
            uint32_t ah0, ah1, ah2, ah3, al0, al1, al2, al3;
            pack_hilo(S[2*kk][0],   S[2*kk][1],   ah0, al0);
            pack_hilo(S[2*kk][2],   S[2*kk][3],   ah1, al1);
            pack_hilo(S[2*kk+1][0], S[2*kk+1][1], ah2, al2);
            pack_hilo(S[2*kk+1][2], S[2*kk+1][3], ah3, al3);
#pragma unroll
            for (int np = 0; np < 4; np++) {
                uint32_t addr = (kk*16 + v_rowsel)*AROW + np*32 + v_colsel;
                uint32_t bh0, bh1, bh2, bh3, bl0, bl1, bl2, bl3;
                ldm4t(bh0, bh1, bh2, bh3, sVh + addr);
                ldm4t(bl0, bl1, bl2, bl3, sVl + addr);
                mma_bf16(O[2*np],   ah0, ah1, ah2, ah3, bh0, bh1);
                mma_bf16(O[2*np],   ah0, ah1, ah2, ah3, bl0, bl1);
                mma_bf16(O[2*np],   al0, al1, al2, al3, bh0, bh1);
                mma_bf16(O[2*np+1], ah0, ah1, ah2, ah3, bh2, bh3);
                mma_bf16(O[2*np+1], ah0, ah1, ah2, ah3, bl2, bl3);
                mma_bf16(O[2*np+1], al0, al1, al2, al3, bh2, bh3);
            }
        }
        __syncthreads();
    }

    float inv0 = 1.f / l0, inv1 = 1.f / l1;
    size_t r0 = (size_t)(b_*NT + i0) * NC + h*HD + qr*2;
    size_t r1 = (size_t)(b_*NT + i1) * NC + h*HD + qr*2;
#pragma unroll
    for (int nt = 0; nt < 8; nt++) {
        split_store2(O[nt][0]*inv0, O[nt][1]*inv0, atth + r0 + nt*8, attl + r0 + nt*8);
        split_store2(O[nt][2]*inv1, O[nt][3]*inv1, atth + r1 + nt*8, attl + r1 + nt*8);
    }
}

// ---------------------------------------------------------------------------

extern "C" void kernel_launch(void* const* d_in, const int* in_sizes, int n_in,
                              void* d_out, int out_size)
{
    const float* x      = (const float*)d_in[0];
    const float* W_attn = (const float*)d_in[1];
    const float* W_proj = (const float*)d_in[2];
    const float* b_proj = (const float*)d_in[3];
    float* out = (float*)d_out;

    __nv_bfloat16 *xh, *xl, *wah, *wal, *wph, *wpl, *qkvh, *qkvl, *atth, *attl;
    cudaGetSymbolAddress((void**)&xh,   g_xh);
    cudaGetSymbolAddress((void**)&xl,   g_xl);
    cudaGetSymbolAddress((void**)&wah,  g_wah);
    cudaGetSymbolAddress((void**)&wal,  g_wal);
    cudaGetSymbolAddress((void**)&wph,  g_wph);
    cudaGetSymbolAddress((void**)&wpl,  g_wpl);
    cudaGetSymbolAddress((void**)&qkvh, g_qkvh);
    cudaGetSymbolAddress((void**)&qkvl, g_qkvl);
    cudaGetSymbolAddress((void**)&atth, g_atth);
    cudaGetSymbolAddress((void**)&attl, g_attl);

    cudaFuncSetAttribute(gemm_mma_kernel,
                         cudaFuncAttributeMaxDynamicSharedMemorySize, GEMM_SMEM);
    cudaFuncSetAttribute(attn_fa2_kernel,
                         cudaFuncAttributeMaxDynamicSharedMemorySize, ATT_SMEM);

    split_kernel<<<8192, 256>>>((const float4*)x,      xh,  xl,  2097152);
    split_kernel<<<3072, 256>>>((const float4*)W_attn, wah, wal, 786432);
    split_kernel<<<1024, 256>>>((const float4*)W_proj, wph, wpl, 262144);

    // QKV: [8192,1024] x [3072,1024]^T -> bf16 hi/lo
    gemm_mma_kernel<<<dim3(12, 64), 256, GEMM_SMEM>>>(
        xh, xl, wah, wal, qkvh, qkvl, nullptr, nullptr, 3072, 0);

    attn_fa2_kernel<<<dim3(16, 64), 256, ATT_SMEM>>>(qkvh, qkvl, atth, attl);

    // proj: [8192,1024] x [1024,1024]^T + bias -> f32 out
    gemm_mma_kernel<<<dim3(4, 64), 256, GEMM_SMEM>>>(
        atth, attl, wph, wpl, nullptr, nullptr, out, b_proj, 1024, 1);
}

// round 8
// speedup vs baseline: 2.9834x; 1.0604x over previous
#include <cuda_runtime.h>
#include <cuda_bf16.h>
#include <math.h>
#include <cstdint>

#define NB 4
#define NT 2048
#define NC 1024
#define NH 16
#define HD 64
#define MM (NB*NT)          // 8192

// ---------------- global scratch (device globals; no runtime alloc) --------
__device__ __nv_bfloat16 g_xh[(size_t)MM*NC],    g_xl[(size_t)MM*NC];
__device__ __nv_bfloat16 g_wah[(size_t)3*NC*NC], g_wal[(size_t)3*NC*NC];
__device__ __nv_bfloat16 g_wph[(size_t)NC*NC],   g_wpl[(size_t)NC*NC];
__device__ __nv_bfloat16 g_qkvh[(size_t)MM*3*NC],g_qkvl[(size_t)MM*3*NC];
__device__ __nv_bfloat16 g_atth[(size_t)MM*NC],  g_attl[(size_t)MM*NC];

// ---------------- helpers --------------------------------------------------
__device__ __forceinline__ uint32_t s2u(const void* p) {
    return (uint32_t)__cvta_generic_to_shared(p);
}
__device__ __forceinline__ void cp16(uint32_t dst, const void* src) {
    asm volatile("cp.async.cg.shared.global [%0], [%1], 16;" :: "r"(dst), "l"(src));
}
__device__ __forceinline__ void cp_commit() {
    asm volatile("cp.async.commit_group;" ::: "memory");
}
__device__ __forceinline__ void cp_wait1() {
    asm volatile("cp.async.wait_group 1;" ::: "memory");
}
__device__ __forceinline__ void cp_wait0() {
    asm volatile("cp.async.wait_group 0;" ::: "memory");
}
__device__ __forceinline__ void ldm4(uint32_t& r0, uint32_t& r1, uint32_t& r2,
                                     uint32_t& r3, uint32_t a) {
    asm volatile("ldmatrix.sync.aligned.m8n8.x4.shared.b16 {%0,%1,%2,%3}, [%4];"
                 : "=r"(r0), "=r"(r1), "=r"(r2), "=r"(r3) : "r"(a));
}
__device__ __forceinline__ void ldm4t(uint32_t& r0, uint32_t& r1, uint32_t& r2,
                                      uint32_t& r3, uint32_t a) {
    asm volatile("ldmatrix.sync.aligned.m8n8.x4.trans.shared.b16 {%0,%1,%2,%3}, [%4];"
                 : "=r"(r0), "=r"(r1), "=r"(r2), "=r"(r3) : "r"(a));
}
__device__ __forceinline__ void mma_bf16(float* c, uint32_t a0, uint32_t a1,
                                         uint32_t a2, uint32_t a3,
                                         uint32_t b0, uint32_t b1) {
    asm volatile("mma.sync.aligned.m16n8k16.row.col.f32.bf16.bf16.f32 "
                 "{%0,%1,%2,%3}, {%4,%5,%6,%7}, {%8,%9}, {%0,%1,%2,%3};"
                 : "+f"(c[0]), "+f"(c[1]), "+f"(c[2]), "+f"(c[3])
                 : "r"(a0), "r"(a1), "r"(a2), "r"(a3), "r"(b0), "r"(b1));
}

// Split fp32 -> bf16 hi + bf16 lo, packed pair stores
__device__ __forceinline__ void split_store2(float x, float y,
                                             __nv_bfloat16* hp, __nv_bfloat16* lp)
{
    __nv_bfloat16 hx = __float2bfloat16(x);
    __nv_bfloat16 hy = __float2bfloat16(y);
    float rx = x - __bfloat162float(hx);
    float ry = y - __bfloat162float(hy);
    *(__nv_bfloat162*)hp = __halves2bfloat162(hx, hy);
    *(__nv_bfloat162*)lp = __halves2bfloat162(__float2bfloat16(rx), __float2bfloat16(ry));
}
__device__ __forceinline__ void pack_hilo(float x, float y, uint32_t& h, uint32_t& l)
{
    __nv_bfloat16 hx = __float2bfloat16(x);
    __nv_bfloat16 hy = __float2bfloat16(y);
    float rx = x - __bfloat162float(hx);
    float ry = y - __bfloat162float(hy);
    __nv_bfloat162 hv = __halves2bfloat162(hx, hy);
    __nv_bfloat162 lv = __halves2bfloat162(__float2bfloat16(rx), __float2bfloat16(ry));
    h = *(uint32_t*)&hv;
    l = *(uint32_t*)&lv;
}

// ---------------- split kernel (f32 -> bf16 hi/lo) -------------------------
__global__ __launch_bounds__(256) void split_kernel(
    const float4* __restrict__ src, __nv_bfloat16* __restrict__ dh,
    __nv_bfloat16* __restrict__ dl, int n4)
{
    int i = blockIdx.x * 256 + threadIdx.x;
    if (i >= n4) return;
    float4 v = src[i];
    split_store2(v.x, v.y, dh + (size_t)i*4,     dl + (size_t)i*4);
    split_store2(v.z, v.w, dh + (size_t)i*4 + 2, dl + (size_t)i*4 + 2);
}

// ---------------------------------------------------------------------------
// mma.sync GEMM on pre-split bf16: C[m][n] = sum_k A[m][k]*B[n][k], K=1024.
// CTA 128x256, 8 warps (warp = 64x64), BK=64, 2-stage cp.async pipeline.
// Tile rows padded to 144 B (conflict-free ldmatrix stride, 36 banks).
// ---------------------------------------------------------------------------
#define GROW 144
#define GABUF (128*GROW)            // 18432
#define GBBUF (256*GROW)            // 36864
#define GSTG  (2*GABUF + 2*GBBUF)   // 110592 per stage
#define GEMM_SMEM (2*GSTG)          // 221184 (also reused as f32 staging)
#define ELD 260                     // f32 staging leading dim (256 + 4 pad)

__device__ __forceinline__ void g_load_stage(
    uint32_t sbase, int st, int kt, int m0, int n0, int tid,
    const __nv_bfloat16* __restrict__ Ah, const __nv_bfloat16* __restrict__ Al,
    const __nv_bfloat16* __restrict__ Bh, const __nv_bfloat16* __restrict__ Bl)
{
    const int koff = kt * 64;
    const uint32_t dbase = sbase + st * GSTG;
    // A hi/lo: 128 rows x 8 chunks of 16B
#pragma unroll
    for (int i = 0; i < 4; i++) {
        int gidx = i * 256 + tid;
        int row = gidx >> 3, c = gidx & 7;
        uint32_t doff = row * GROW + c * 16;
        size_t soff = (size_t)(m0 + row) * 1024 + koff + c * 8;
        cp16(dbase + doff,         Ah + soff);
        cp16(dbase + GABUF + doff, Al + soff);
    }
    // B hi/lo: 256 rows x 8 chunks of 16B
#pragma unroll
    for (int i = 0; i < 8; i++) {
        int gidx = i * 256 + tid;
        int row = gidx >> 3, c = gidx & 7;
        uint32_t doff = row * GROW + c * 16;
        size_t soff = (size_t)(n0 + row) * 1024 + koff + c * 8;
        cp16(dbase + 2*GABUF + doff,         Bh + soff);
        cp16(dbase + 2*GABUF + GBBUF + doff, Bl + soff);
    }
    cp_commit();
}

__global__ __launch_bounds__(256, 1) void gemm_mma_kernel(
    const __nv_bfloat16* __restrict__ Ah, const __nv_bfloat16* __restrict__ Al,
    const __nv_bfloat16* __restrict__ Bh, const __nv_bfloat16* __restrict__ Bl,
    __nv_bfloat16* __restrict__ outH, __nv_bfloat16* __restrict__ outL,
    float* __restrict__ outF, const float* __restrict__ bias,
    int ldc, int mode)
{
    extern __shared__ char sm[];
    const uint32_t sbase = s2u(sm);
    const int tid  = threadIdx.x;
    const int warp = tid >> 5;
    const int lid  = tid & 31;
    const int g    = lid >> 2;
    const int qr   = lid & 3;
    const int grp  = lid >> 3;
    const int rr   = lid & 7;

    const int m0 = blockIdx.y << 7;
    const int n0 = blockIdx.x << 8;
    const int mw = (warp >> 2) * 64;   // 0 or 64
    const int nw = (warp & 3) * 64;    // 0..192

    const uint32_t a_rowsel = ((grp & 1) ? 8 : 0) + rr;
    const uint32_t a_colsel = (grp >= 2) ? 16 : 0;
    const uint32_t b_rowsel = ((grp >= 2) ? 8 : 0) + rr;
    const uint32_t b_colsel = (grp & 1) ? 16 : 0;

    float acc[4][8][4];
#pragma unroll
    for (int mt = 0; mt < 4; mt++)
#pragma unroll
        for (int nt = 0; nt < 8; nt++) {
            acc[mt][nt][0] = 0.f; acc[mt][nt][1] = 0.f;
            acc[mt][nt][2] = 0.f; acc[mt][nt][3] = 0.f;
        }

    g_load_stage(sbase, 0, 0, m0, n0, tid, Ah, Al, Bh, Bl);

    int stidx = 0;
    for (int kt = 0; kt < 16; kt++) {
        cp_wait0();
        __syncthreads();

        if (kt + 1 < 16)
            g_load_stage(sbase, stidx ^ 1, kt + 1, m0, n0, tid, Ah, Al, Bh, Bl);

        const uint32_t sb  = sbase + stidx * GSTG;
        const uint32_t sAh = sb;
        const uint32_t sAl = sb + GABUF;
        const uint32_t sBh = sb + 2*GABUF;
        const uint32_t sBl = sb + 2*GABUF + GBBUF;

#pragma unroll
        for (int kk = 0; kk < 4; kk++) {
            uint32_t ah[4][4], al[4][4];
#pragma unroll
            for (int mt = 0; mt < 4; mt++) {
                uint32_t ra = (mw + mt*16 + a_rowsel) * GROW + kk*32 + a_colsel;
                ldm4(ah[mt][0], ah[mt][1], ah[mt][2], ah[mt][3], sAh + ra);
                ldm4(al[mt][0], al[mt][1], al[mt][2], al[mt][3], sAl + ra);
            }
#pragma unroll
            for (int nc = 0; nc < 4; nc++) {
                uint32_t rb = (nw + nc*16 + b_rowsel) * GROW + kk*32 + b_colsel;
                uint32_t bh0, bh1, bh2, bh3, bl0, bl1, bl2, bl3;
                ldm4(bh0, bh1, bh2, bh3, sBh + rb);
                ldm4(bl0, bl1, bl2, bl3, sBl + rb);
#pragma unroll
                for (int mt = 0; mt < 4; mt++) {
                    mma_bf16(acc[mt][2*nc],   ah[mt][0], ah[mt][1], ah[mt][2], ah[mt][3], bh0, bh1);
                    mma_bf16(acc[mt][2*nc+1], ah[mt][0], ah[mt][1], ah[mt][2], ah[mt][3], bh2, bh3);
                }
#pragma unroll
                for (int mt = 0; mt < 4; mt++) {
                    mma_bf16(acc[mt][2*nc],   ah[mt][0], ah[mt][1], ah[mt][2], ah[mt][3], bl0, bl1);
                    mma_bf16(acc[mt][2*nc+1], ah[mt][0], ah[mt][1], ah[mt][2], ah[mt][3], bl2, bl3);
                }
#pragma unroll
                for (int mt = 0; mt < 4; mt++) {
                    mma_bf16(acc[mt][2*nc],   al[mt][0], al[mt][1], al[mt][2], al[mt][3], bh0, bh1);
                    mma_bf16(acc[mt][2*nc+1], al[mt][0], al[mt][1], al[mt][2], al[mt][3], bh2, bh3);
                }
            }
        }
        stidx ^= 1;
    }

    // ---------------- epilogue: stage f32 in smem, write coalesced ---------
    __syncthreads();
    float* Sst = (float*)sm;    // [128][ELD]
#pragma unroll
    for (int mt = 0; mt < 4; mt++) {
        int row = mw + mt*16 + g;
#pragma unroll
        for (int nt = 0; nt < 8; nt++) {
            int col = nw + nt*8 + qr*2;
            *(float2*)&Sst[row*ELD + col]       = make_float2(acc[mt][nt][0], acc[mt][nt][1]);
            *(float2*)&Sst[(row+8)*ELD + col]   = make_float2(acc[mt][nt][2], acc[mt][nt][3]);
        }
    }
    __syncthreads();

    if (mode == 0) {
#pragma unroll 1
        for (int r = 0; r < 16; r++) {
            int row = warp*16 + r;
            size_t ob = (size_t)(m0 + row) * ldc + n0;
#pragma unroll
            for (int blk = 0; blk < 4; blk++) {
                int c = blk*64 + lid*2;
                float2 v = *(float2*)&Sst[row*ELD + c];
                split_store2(v.x, v.y, outH + ob + c, outL + ob + c);
            }
        }
    } else {
#pragma unroll 1
        for (int r = 0; r < 16; r++) {
            int row = warp*16 + r;
            size_t ob = (size_t)(m0 + row) * ldc + n0;
#pragma unroll
            for (int blk = 0; blk < 2; blk++) {
                int c = blk*128 + lid*4;
                float4 v = *(float4*)&Sst[row*ELD + c];
                v.x += bias[n0 + c];     v.y += bias[n0 + c + 1];
                v.z += bias[n0 + c + 2]; v.w += bias[n0 + c + 3];
                *(float4*)(outF + ob + c) = v;
            }
        }
    }
}

// ---------------------------------------------------------------------------
// Register-resident flash attention (R5 core; qt reversed for load balance).
// ---------------------------------------------------------------------------
#define AROW 144
#define AQ_BYTES   (128*AROW)
#define AKV_BUF    (64*AROW)
#define AKV_STAGE  (4*AKV_BUF)
#define AKV_OFF    (2*AQ_BYTES)
#define ATT_SMEM   (AKV_OFF + 2*AKV_STAGE)

__device__ __forceinline__ void attn_cp_kv(
    uint32_t sbase, int st, const __nv_bfloat16* qkvh, const __nv_bfloat16* qkvl,
    size_t rowbase, int tid)
{
    int b = tid >> 6;
    int row = tid & 63;
    const __nv_bfloat16* src = ((b & 1) ? qkvl : qkvh)
        + rowbase + ((b >> 1) ? 2048 : 1024) + (size_t)row * 3072;
    uint32_t dst = sbase + AKV_OFF + st*AKV_STAGE + b*AKV_BUF + row*AROW;
#pragma unroll
    for (int c = 0; c < 8; c++) cp16(dst + c*16, src + c*8);
    cp_commit();
}

__global__ __launch_bounds__(256) void attn_fa2_kernel(
    const __nv_bfloat16* __restrict__ qkvh, const __nv_bfloat16* __restrict__ qkvl,
    __nv_bfloat16* __restrict__ atth, __nv_bfloat16* __restrict__ attl)
{
    extern __shared__ char smraw[];
    const uint32_t sbase = s2u(smraw);

    const int tid  = threadIdx.x;
    const int warp = tid >> 5;
    const int lid  = tid & 31;
    const int g    = lid >> 2;
    const int qr   = lid & 3;
    const int grp  = lid >> 3;
    const int rr   = lid & 7;

    const int qt = (gridDim.x - 1) - blockIdx.x;   // longest tiles first
    const int bh = blockIdx.y;
    const int b_ = bh >> 4;
    const int h  = bh & 15;
    const int t0 = qt * 128;

    {
        int qb  = tid >> 7;
        int row = tid & 127;
        const __nv_bfloat16* src = (qb ? qkvl : qkvh)
            + (size_t)(b_*NT + t0 + row) * 3072 + h*HD;
        uint32_t dst = sbase + qb*AQ_BYTES + row*AROW;
#pragma unroll
        for (int c = 0; c < 8; c++) cp16(dst + c*16, src + c*8);
    }
    cp_commit();

    attn_cp_kv(sbase, 0, qkvh, qkvl, (size_t)(b_*NT) * 3072 + h*HD, tid);

    cp_wait1();
    __syncthreads();

    uint32_t aqh[4][4], aql[4][4];
    {
        uint32_t rowoff = (16*warp + ((grp & 1) ? 8 : 0) + rr) * AROW
                        + ((grp >= 2) ? 16 : 0);
#pragma unroll
        for (int kk = 0; kk < 4; kk++) {
            ldm4(aqh[kk][0], aqh[kk][1], aqh[kk][2], aqh[kk][3],
                 sbase + rowoff + kk*32);
            ldm4(aql[kk][0], aql[kk][1], aql[kk][2], aql[kk][3],
                 sbase + AQ_BYTES + rowoff + kk*32);
        }
    }

    float O[8][4];
#pragma unroll
    for (int nt = 0; nt < 8; nt++) {
        O[nt][0] = 0.f; O[nt][1] = 0.f; O[nt][2] = 0.f; O[nt][3] = 0.f;
    }
    float m0 = -1e30f, m1 = -1e30f, l0 = 0.f, l1 = 0.f;

    const int i0 = t0 + 16*warp + g;
    const int i1 = i0 + 8;
    const int njt = 2*qt + 2;

    const uint32_t k_rowsel = ((grp >= 2) ? 8 : 0) + rr;
    const uint32_t k_colsel = ((grp & 1) ? 16 : 0);
    const uint32_t v_rowsel = ((grp & 1) ? 8 : 0) + rr;
    const uint32_t v_colsel = ((grp >= 2) ? 16 : 0);

    for (int jt = 0; jt < njt; jt++) {
        const int st = jt & 1;
        if (jt + 1 < njt)
            attn_cp_kv(sbase, st ^ 1, qkvh, qkvl,
                       (size_t)(b_*NT + (jt+1)*64) * 3072 + h*HD, tid);
        if (jt + 1 < njt) cp_wait1(); else cp_wait0();
        __syncthreads();

        const uint32_t sK = sbase + AKV_OFF + st*AKV_STAGE;
        const uint32_t sKh = sK;
        const uint32_t sKl = sK + AKV_BUF;
        const uint32_t sVh = sK + 2*AKV_BUF;
        const uint32_t sVl = sK + 3*AKV_BUF;

        float S[8][4];
#pragma unroll
        for (int nt = 0; nt < 8; nt++) {
            S[nt][0] = 0.f; S[nt][1] = 0.f; S[nt][2] = 0.f; S[nt][3] = 0.f;
        }
#pragma unroll
        for (int kk = 0; kk < 4; kk++) {
#pragma unroll
            for (int np = 0; np < 4; np++) {
                uint32_t addr = (np*16 + k_rowsel)*AROW + kk*32 + k_colsel;
                uint32_t bh0, bh1, bh2, bh3, bl0, bl1, bl2, bl3;
                ldm4(bh0, bh1, bh2, bh3, sKh + addr);
                ldm4(bl0, bl1, bl2, bl3, sKl + addr);
                mma_bf16(S[2*np],   aqh[kk][0], aqh[kk][1], aqh[kk][2], aqh[kk][3], bh0, bh1);
                mma_bf16(S[2*np],   aqh[kk][0], aqh[kk][1], aqh[kk][2], aqh[kk][3], bl0, bl1);
                mma_bf16(S[2*np],   aql[kk][0], aql[kk][1], aql[kk][2], aql[kk][3], bh0, bh1);
                mma_bf16(S[2*np+1], aqh[kk][0], aqh[kk][1], aqh[kk][2], aqh[kk][3], bh2, bh3);
                mma_bf16(S[2*np+1], aqh[kk][0], aqh[kk][1], aqh[kk][2], aqh[kk][3], bl2, bl3);
                mma_bf16(S[2*np+1], aql[kk][0], aql[kk][1], aql[kk][2], aql[kk][3], bh2, bh3);
            }
        }

        const bool need_mask = (jt >= 2*qt);
#pragma unroll
        for (int nt = 0; nt < 8; nt++) {
            int jb = jt*64 + nt*8 + qr*2;
            float s0 = S[nt][0] * 8.f, s1 = S[nt][1] * 8.f;
            float s2 = S[nt][2] * 8.f, s3 = S[nt][3] * 8.f;
            if (need_mask) {
                if (jb     > i0) s0 = -1e30f;
                if (jb + 1 > i0) s1 = -1e30f;
                if (jb     > i1) s2 = -1e30f;
                if (jb + 1 > i1) s3 = -1e30f;
            }
            S[nt][0] = s0; S[nt][1] = s1; S[nt][2] = s2; S[nt][3] = s3;
        }

        float mx0 = -1e30f, mx1 = -1e30f;
#pragma unroll
        for (int nt = 0; nt < 8; nt++) {
            mx0 = fmaxf(mx0, fmaxf(S[nt][0], S[nt][1]));
            mx1 = fmaxf(mx1, fmaxf(S[nt][2], S[nt][3]));
        }
        mx0 = fmaxf(mx0, __shfl_xor_sync(0xffffffffu, mx0, 1));
        mx0 = fmaxf(mx0, __shfl_xor_sync(0xffffffffu, mx0, 2));
        mx1 = fmaxf(mx1, __shfl_xor_sync(0xffffffffu, mx1, 1));
        mx1 = fmaxf(mx1, __shfl_xor_sync(0xffffffffu, mx1, 2));

        float mn0 = fmaxf(m0, mx0), mn1 = fmaxf(m1, mx1);
        float corr0 = __expf(m0 - mn0), corr1 = __expf(m1 - mn1);
        m0 = mn0; m1 = mn1;

        float sum0 = 0.f, sum1 = 0.f;
#pragma unroll
        for (int nt = 0; nt < 8; nt++) {
            float p0 = __expf(S[nt][0] - mn0);
            float p1 = __expf(S[nt][1] - mn0);
            float p2 = __expf(S[nt][2] - mn1);
            float p3 = __expf(S[nt][3] - mn1);
            sum0 += p0 + p1; sum1 += p2 + p3;
            S[nt][0] = p0; S[nt][1] = p1; S[nt][2] = p2; S[nt][3] = p3;
        }
        sum0 += __shfl_xor_sync(0xffffffffu, sum0, 1);
        sum0 += __shfl_xor_sync(0xffffffffu, sum0, 2);
        sum1 += __shfl_xor_sync(0xffffffffu, sum1, 1);
        sum1 += __shfl_xor_sync(0xffffffffu, sum1, 2);
        l0 = l0 * corr0 + sum0;
        l1 = l1 * corr1 + sum1;

#pragma unroll
        for (int nt = 0; nt < 8; nt++) {
            O[nt][0] *= corr0; O[nt][1] *= corr0;
            O[nt][2] *= corr1; O[nt][3] *= corr1;
        }

#pragma unroll
        for (int kk = 0; kk < 4; kk++) {
            uint32_t ah0, ah1, ah2, ah3, al0, al1, al2, al3;
            pack_hilo(S[2*kk][0],   S[2*kk][1],   ah0, al0);
            pack_hilo(S[2*kk][2],   S[2*kk][3],   ah1, al1);
            pack_hilo(S[2*kk+1][0], S[2*kk+1][1], ah2, al2);
            pack_hilo(S[2*kk+1][2], S[2*kk+1][3], ah3, al3);
#pragma unroll
            for (int np = 0; np < 4; np++) {
                uint32_t addr = (kk*16 + v_rowsel)*AROW + np*32 + v_colsel;
                uint32_t bh0, bh1, bh2, bh3, bl0, bl1, bl2, bl3;
                ldm4t(bh0, bh1, bh2, bh3, sVh + addr);
                ldm4t(bl0, bl1, bl2, bl3, sVl + addr);
                mma_bf16(O[2*np],   ah0, ah1, ah2, ah3, bh0, bh1);
                mma_bf16(O[2*np],   ah0, ah1, ah2, ah3, bl0, bl1);
                mma_bf16(O[2*np],   al0, al1, al2, al3, bh0, bh1);
                mma_bf16(O[2*np+1], ah0, ah1, ah2, ah3, bh2, bh3);
                mma_bf16(O[2*np+1], ah0, ah1, ah2, ah3, bl2, bl3);
                mma_bf16(O[2*np+1], al0, al1, al2, al3, bh2, bh3);
            }
        }
        __syncthreads();
    }

    float inv0 = 1.f / l0, inv1 = 1.f / l1;
    size_t r0 = (size_t)(b_*NT + i0) * NC + h*HD + qr*2;
    size_t r1 = (size_t)(b_*NT + i1) * NC + h*HD + qr*2;
#pragma unroll
    for (int nt = 0; nt < 8; nt++) {
        split_store2(O[nt][0]*inv0, O[nt][1]*inv0, atth + r0 + nt*8, attl + r0 + nt*8);
        split_store2(O[nt][2]*inv1, O[nt][3]*inv1, atth + r1 + nt*8, attl + r1 + nt*8);
    }
}

// ---------------------------------------------------------------------------

extern "C" void kernel_launch(void* const* d_in, const int* in_sizes, int n_in,
                              void* d_out, int out_size)
{
    const float* x      = (const float*)d_in[0];
    const float* W_attn = (const float*)d_in[1];
    const float* W_proj = (const float*)d_in[2];
    const float* b_proj = (const float*)d_in[3];
    float* out = (float*)d_out;

    __nv_bfloat16 *xh, *xl, *wah, *wal, *wph, *wpl, *qkvh, *qkvl, *atth, *attl;
    cudaGetSymbolAddress((void**)&xh,   g_xh);
    cudaGetSymbolAddress((void**)&xl,   g_xl);
    cudaGetSymbolAddress((void**)&wah,  g_wah);
    cudaGetSymbolAddress((void**)&wal,  g_wal);
    cudaGetSymbolAddress((void**)&wph,  g_wph);
    cudaGetSymbolAddress((void**)&wpl,  g_wpl);
    cudaGetSymbolAddress((void**)&qkvh, g_qkvh);
    cudaGetSymbolAddress((void**)&qkvl, g_qkvl);
    cudaGetSymbolAddress((void**)&atth, g_atth);
    cudaGetSymbolAddress((void**)&attl, g_attl);

    cudaFuncSetAttribute(gemm_mma_kernel,
                         cudaFuncAttributeMaxDynamicSharedMemorySize, GEMM_SMEM);
    cudaFuncSetAttribute(attn_fa2_kernel,
                         cudaFuncAttributeMaxDynamicSharedMemorySize, ATT_SMEM);

    split_kernel<<<8192, 256>>>((const float4*)x,      xh,  xl,  2097152);
    split_kernel<<<3072, 256>>>((const float4*)W_attn, wah, wal, 786432);
    split_kernel<<<1024, 256>>>((const float4*)W_proj, wph, wpl, 262144);

    // QKV: [8192,1024] x [3072,1024]^T -> bf16 hi/lo
    gemm_mma_kernel<<<dim3(12, 64), 256, GEMM_SMEM>>>(
        xh, xl, wah, wal, qkvh, qkvl, nullptr, nullptr, 3072, 0);

    attn_fa2_kernel<<<dim3(16, 64), 256, ATT_SMEM>>>(qkvh, qkvl, atth, attl);

    // proj: [8192,1024] x [1024,1024]^T + bias -> f32 out
    gemm_mma_kernel<<<dim3(4, 64), 256, GEMM_SMEM>>>(
        atth, attl, wph, wpl, nullptr, nullptr, out, b_proj, 1024, 1);
}

// round 9
// speedup vs baseline: 3.1263x; 1.0479x over previous
#include <cuda_runtime.h>
#include <cuda_bf16.h>
#include <math.h>
#include <cstdint>

#define NB 4
#define NT 2048
#define NC 1024
#define NH 16
#define HD 64
#define MM (NB*NT)          // 8192

// ---------------- global scratch (device globals; no runtime alloc) --------
__device__ __nv_bfloat16 g_xh[(size_t)MM*NC],    g_xl[(size_t)MM*NC];
__device__ __nv_bfloat16 g_wah[(size_t)3*NC*NC], g_wal[(size_t)3*NC*NC];
__device__ __nv_bfloat16 g_wph[(size_t)NC*NC],   g_wpl[(size_t)NC*NC];
__device__ __nv_bfloat16 g_qkvh[(size_t)MM*3*NC],g_qkvl[(size_t)MM*3*NC];
__device__ __nv_bfloat16 g_atth[(size_t)MM*NC],  g_attl[(size_t)MM*NC];

// ---------------- helpers --------------------------------------------------
__device__ __forceinline__ uint32_t s2u(const void* p) {
    return (uint32_t)__cvta_generic_to_shared(p);
}
__device__ __forceinline__ void cp16(uint32_t dst, const void* src) {
    asm volatile("cp.async.cg.shared.global [%0], [%1], 16;" :: "r"(dst), "l"(src));
}
__device__ __forceinline__ void cp_commit() {
    asm volatile("cp.async.commit_group;" ::: "memory");
}
__device__ __forceinline__ void cp_wait1() {
    asm volatile("cp.async.wait_group 1;" ::: "memory");
}
__device__ __forceinline__ void cp_wait0() {
    asm volatile("cp.async.wait_group 0;" ::: "memory");
}
__device__ __forceinline__ void ldm4(uint32_t& r0, uint32_t& r1, uint32_t& r2,
                                     uint32_t& r3, uint32_t a) {
    asm volatile("ldmatrix.sync.aligned.m8n8.x4.shared.b16 {%0,%1,%2,%3}, [%4];"
                 : "=r"(r0), "=r"(r1), "=r"(r2), "=r"(r3) : "r"(a));
}
__device__ __forceinline__ void ldm4t(uint32_t& r0, uint32_t& r1, uint32_t& r2,
                                      uint32_t& r3, uint32_t a) {
    asm volatile("ldmatrix.sync.aligned.m8n8.x4.trans.shared.b16 {%0,%1,%2,%3}, [%4];"
                 : "=r"(r0), "=r"(r1), "=r"(r2), "=r"(r3) : "r"(a));
}
__device__ __forceinline__ void mma_bf16(float* c, uint32_t a0, uint32_t a1,
                                         uint32_t a2, uint32_t a3,
                                         uint32_t b0, uint32_t b1) {
    asm volatile("mma.sync.aligned.m16n8k16.row.col.f32.bf16.bf16.f32 "
                 "{%0,%1,%2,%3}, {%4,%5,%6,%7}, {%8,%9}, {%0,%1,%2,%3};"
                 : "+f"(c[0]), "+f"(c[1]), "+f"(c[2]), "+f"(c[3])
                 : "r"(a0), "r"(a1), "r"(a2), "r"(a3), "r"(b0), "r"(b1));
}

// Split fp32 -> bf16 hi + bf16 lo, packed pair stores
__device__ __forceinline__ void split_store2(float x, float y,
                                             __nv_bfloat16* hp, __nv_bfloat16* lp)
{
    __nv_bfloat16 hx = __float2bfloat16(x);
    __nv_bfloat16 hy = __float2bfloat16(y);
    float rx = x - __bfloat162float(hx);
    float ry = y - __bfloat162float(hy);
    *(__nv_bfloat162*)hp = __halves2bfloat162(hx, hy);
    *(__nv_bfloat162*)lp = __halves2bfloat162(__float2bfloat16(rx), __float2bfloat16(ry));
}
__device__ __forceinline__ void pack_hilo(float x, float y, uint32_t& h, uint32_t& l)
{
    __nv_bfloat16 hx = __float2bfloat16(x);
    __nv_bfloat16 hy = __float2bfloat16(y);
    float rx = x - __bfloat162float(hx);
    float ry = y - __bfloat162float(hy);
    __nv_bfloat162 hv = __halves2bfloat162(hx, hy);
    __nv_bfloat162 lv = __halves2bfloat162(__float2bfloat16(rx), __float2bfloat16(ry));
    h = *(uint32_t*)&hv;
    l = *(uint32_t*)&lv;
}

// ---------------- split kernel (f32 -> bf16 hi/lo) -------------------------
__global__ __launch_bounds__(256) void split_kernel(
    const float4* __restrict__ src, __nv_bfloat16* __restrict__ dh,
    __nv_bfloat16* __restrict__ dl, int n4)
{
    int i = blockIdx.x * 256 + threadIdx.x;
    if (i >= n4) return;
    float4 v = src[i];
    split_store2(v.x, v.y, dh + (size_t)i*4,     dl + (size_t)i*4);
    split_store2(v.z, v.w, dh + (size_t)i*4 + 2, dl + (size_t)i*4 + 2);
}

// ---------------------------------------------------------------------------
// mma.sync GEMM on pre-split bf16: C[m][n] = sum_k A[m][k]*B[n][k], K=1024.
// CTA 128x256, 8 warps (warp = 64x64), BK=64, 2-stage cp.async pipeline,
// prefetch issue split around the first half of the compute.
// ---------------------------------------------------------------------------
#define GROW 144
#define GABUF (128*GROW)            // 18432
#define GBBUF (256*GROW)            // 36864
#define GSTG  (2*GABUF + 2*GBBUF)   // 110592 per stage
#define GEMM_SMEM (2*GSTG)          // 221184 (also reused as f32 staging)
#define ELD 260                     // f32 staging leading dim (256 + 4 pad)

__device__ __forceinline__ void g_load_A(
    uint32_t sbase, int st, int kt, int m0, int tid,
    const __nv_bfloat16* __restrict__ Ah, const __nv_bfloat16* __restrict__ Al)
{
    const int koff = kt * 64;
    const uint32_t dbase = sbase + st * GSTG;
#pragma unroll
    for (int i = 0; i < 4; i++) {
        int gidx = i * 256 + tid;
        int row = gidx >> 3, c = gidx & 7;
        uint32_t doff = row * GROW + c * 16;
        size_t soff = (size_t)(m0 + row) * 1024 + koff + c * 8;
        cp16(dbase + doff,         Ah + soff);
        cp16(dbase + GABUF + doff, Al + soff);
    }
}
__device__ __forceinline__ void g_load_B(
    uint32_t sbase, int st, int kt, int n0, int tid,
    const __nv_bfloat16* __restrict__ Bh, const __nv_bfloat16* __restrict__ Bl)
{
    const int koff = kt * 64;
    const uint32_t dbase = sbase + st * GSTG + 2*GABUF;
#pragma unroll
    for (int i = 0; i < 8; i++) {
        int gidx = i * 256 + tid;
        int row = gidx >> 3, c = gidx & 7;
        uint32_t doff = row * GROW + c * 16;
        size_t soff = (size_t)(n0 + row) * 1024 + koff + c * 8;
        cp16(dbase + doff,         Bh + soff);
        cp16(dbase + GBBUF + doff, Bl + soff);
    }
}

__global__ __launch_bounds__(256, 1) void gemm_mma_kernel(
    const __nv_bfloat16* __restrict__ Ah, const __nv_bfloat16* __restrict__ Al,
    const __nv_bfloat16* __restrict__ Bh, const __nv_bfloat16* __restrict__ Bl,
    __nv_bfloat16* __restrict__ outH, __nv_bfloat16* __restrict__ outL,
    float* __restrict__ outF, const float* __restrict__ bias,
    int ldc, int mode)
{
    extern __shared__ char sm[];
    const uint32_t sbase = s2u(sm);
    const int tid  = threadIdx.x;
    const int warp = tid >> 5;
    const int lid  = tid & 31;
    const int g    = lid >> 2;
    const int qr   = lid & 3;
    const int grp  = lid >> 3;
    const int rr   = lid & 7;

    const int m0 = blockIdx.y << 7;
    const int n0 = blockIdx.x << 8;
    const int mw = (warp >> 2) * 64;   // 0 or 64
    const int nw = (warp & 3) * 64;    // 0..192

    const uint32_t a_rowsel = ((grp & 1) ? 8 : 0) + rr;
    const uint32_t a_colsel = (grp >= 2) ? 16 : 0;
    const uint32_t b_rowsel = ((grp >= 2) ? 8 : 0) + rr;
    const uint32_t b_colsel = (grp & 1) ? 16 : 0;

    float acc[4][8][4];
#pragma unroll
    for (int mt = 0; mt < 4; mt++)
#pragma unroll
        for (int nt = 0; nt < 8; nt++) {
            acc[mt][nt][0] = 0.f; acc[mt][nt][1] = 0.f;
            acc[mt][nt][2] = 0.f; acc[mt][nt][3] = 0.f;
        }

    g_load_A(sbase, 0, 0, m0, tid, Ah, Al);
    g_load_B(sbase, 0, 0, n0, tid, Bh, Bl);
    cp_commit();

    int stidx = 0;
    for (int kt = 0; kt < 16; kt++) {
        cp_wait0();
        __syncthreads();

        const uint32_t sb  = sbase + stidx * GSTG;
        const uint32_t sAh = sb;
        const uint32_t sAl = sb + GABUF;
        const uint32_t sBh = sb + 2*GABUF;
        const uint32_t sBl = sb + 2*GABUF + GBBUF;

        // prefetch A-half for next stage, compute first half, then B-half.
        if (kt + 1 < 16)
            g_load_A(sbase, stidx ^ 1, kt + 1, m0, tid, Ah, Al);

#pragma unroll
        for (int half = 0; half < 2; half++) {
#pragma unroll
            for (int kq = 0; kq < 2; kq++) {
                const int kk = half*2 + kq;
                uint32_t ah[4][4], al[4][4];
#pragma unroll
                for (int mt = 0; mt < 4; mt++) {
                    uint32_t ra = (mw + mt*16 + a_rowsel) * GROW + kk*32 + a_colsel;
                    ldm4(ah[mt][0], ah[mt][1], ah[mt][2], ah[mt][3], sAh + ra);
                    ldm4(al[mt][0], al[mt][1], al[mt][2], al[mt][3], sAl + ra);
                }
#pragma unroll
                for (int nc = 0; nc < 4; nc++) {
                    uint32_t rb = (nw + nc*16 + b_rowsel) * GROW + kk*32 + b_colsel;
                    uint32_t bh0, bh1, bh2, bh3, bl0, bl1, bl2, bl3;
                    ldm4(bh0, bh1, bh2, bh3, sBh + rb);
                    ldm4(bl0, bl1, bl2, bl3, sBl + rb);
#pragma unroll
                    for (int mt = 0; mt < 4; mt++) {
                        mma_bf16(acc[mt][2*nc],   ah[mt][0], ah[mt][1], ah[mt][2], ah[mt][3], bh0, bh1);
                        mma_bf16(acc[mt][2*nc+1], ah[mt][0], ah[mt][1], ah[mt][2], ah[mt][3], bh2, bh3);
                    }
#pragma unroll
                    for (int mt = 0; mt < 4; mt++) {
                        mma_bf16(acc[mt][2*nc],   ah[mt][0], ah[mt][1], ah[mt][2], ah[mt][3], bl0, bl1);
                        mma_bf16(acc[mt][2*nc+1], ah[mt][0], ah[mt][1], ah[mt][2], ah[mt][3], bl2, bl3);
                    }
#pragma unroll
                    for (int mt = 0; mt < 4; mt++) {
                        mma_bf16(acc[mt][2*nc],   al[mt][0], al[mt][1], al[mt][2], al[mt][3], bh0, bh1);
                        mma_bf16(acc[mt][2*nc+1], al[mt][0], al[mt][1], al[mt][2], al[mt][3], bh2, bh3);
                    }
                }
            }
            if (half == 0) {
                if (kt + 1 < 16)
                    g_load_B(sbase, stidx ^ 1, kt + 1, n0, tid, Bh, Bl);
                cp_commit();
            }
        }
        stidx ^= 1;
    }

    // ---------------- epilogue: stage f32 in smem, write coalesced ---------
    __syncthreads();
    float* Sst = (float*)sm;    // [128][ELD]
#pragma unroll
    for (int mt = 0; mt < 4; mt++) {
        int row = mw + mt*16 + g;
#pragma unroll
        for (int nt = 0; nt < 8; nt++) {
            int col = nw + nt*8 + qr*2;
            *(float2*)&Sst[row*ELD + col]       = make_float2(acc[mt][nt][0], acc[mt][nt][1]);
            *(float2*)&Sst[(row+8)*ELD + col]   = make_float2(acc[mt][nt][2], acc[mt][nt][3]);
        }
    }
    __syncthreads();

    if (mode == 0) {
#pragma unroll 1
        for (int r = 0; r < 16; r++) {
            int row = warp*16 + r;
            size_t ob = (size_t)(m0 + row) * ldc + n0;
#pragma unroll
            for (int blk = 0; blk < 4; blk++) {
                int c = blk*64 + lid*2;
                float2 v = *(float2*)&Sst[row*ELD + c];
                split_store2(v.x, v.y, outH + ob + c, outL + ob + c);
            }
        }
    } else {
#pragma unroll 1
        for (int r = 0; r < 16; r++) {
            int row = warp*16 + r;
            size_t ob = (size_t)(m0 + row) * ldc + n0;
#pragma unroll
            for (int blk = 0; blk < 2; blk++) {
                int c = blk*128 + lid*4;
                float4 v = *(float4*)&Sst[row*ELD + c];
                v.x += bias[n0 + c];     v.y += bias[n0 + c + 1];
                v.z += bias[n0 + c + 2]; v.w += bias[n0 + c + 3];
                *(float4*)(outF + ob + c) = v;
            }
        }
    }
}

// ---------------------------------------------------------------------------
// Register-resident flash attention. kv macro-tile = 128 rows (2 x 64 subs
// per barrier window), double-buffered. CTA = 128 q rows x one (b,h).
// ---------------------------------------------------------------------------
#define AROW 144
#define AQ_BYTES   (128*AROW)          // 18432
#define AKV_BUF    (128*AROW)          // 18432 per tensor buffer
#define AKV_STAGE  (4*AKV_BUF)         // 73728
#define AKV_OFF    (2*AQ_BYTES)        // 36864
#define ATT_SMEM   (AKV_OFF + 2*AKV_STAGE)   // 184320

__device__ __forceinline__ void attn_cp_kv(
    uint32_t sbase, int st, const __nv_bfloat16* qkvh, const __nv_bfloat16* qkvl,
    size_t rowbase, int tid)
{
    int b = tid >> 6;           // 0:Kh 1:Kl 2:Vh 3:Vl
    int r0 = tid & 63;
    const __nv_bfloat16* base = ((b & 1) ? qkvl : qkvh)
        + rowbase + ((b >> 1) ? 2048 : 1024);
    uint32_t dbuf = sbase + AKV_OFF + st*AKV_STAGE + b*AKV_BUF;
#pragma unroll
    for (int half = 0; half < 2; half++) {
        int row = r0 + half*64;
        const __nv_bfloat16* src = base + (size_t)row * 3072;
        uint32_t dst = dbuf + row*AROW;
#pragma unroll
        for (int c = 0; c < 8; c++) cp16(dst + c*16, src + c*8);
    }
    cp_commit();
}

__global__ __launch_bounds__(256) void attn_fa2_kernel(
    const __nv_bfloat16* __restrict__ qkvh, const __nv_bfloat16* __restrict__ qkvl,
    __nv_bfloat16* __restrict__ atth, __nv_bfloat16* __restrict__ attl)
{
    extern __shared__ char smraw[];
    const uint32_t sbase = s2u(smraw);

    const int tid  = threadIdx.x;
    const int warp = tid >> 5;
    const int lid  = tid & 31;
    const int g    = lid >> 2;
    const int qr   = lid & 3;
    const int grp  = lid >> 3;
    const int rr   = lid & 7;

    const int qt = (gridDim.x - 1) - blockIdx.x;   // longest tiles first
    const int bh = blockIdx.y;
    const int b_ = bh >> 4;
    const int h  = bh & 15;
    const int t0 = qt * 128;

    {
        int qb  = tid >> 7;
        int row = tid & 127;
        const __nv_bfloat16* src = (qb ? qkvl : qkvh)
            + (size_t)(b_*NT + t0 + row) * 3072 + h*HD;
        uint32_t dst = sbase + qb*AQ_BYTES + row*AROW;
#pragma unroll
        for (int c = 0; c < 8; c++) cp16(dst + c*16, src + c*8);
    }
    cp_commit();

    attn_cp_kv(sbase, 0, qkvh, qkvl, (size_t)(b_*NT) * 3072 + h*HD, tid);

    cp_wait1();
    __syncthreads();

    uint32_t aqh[4][4], aql[4][4];
    {
        uint32_t rowoff = (16*warp + ((grp & 1) ? 8 : 0) + rr) * AROW
                        + ((grp >= 2) ? 16 : 0);
#pragma unroll
        for (int kk = 0; kk < 4; kk++) {
            ldm4(aqh[kk][0], aqh[kk][1], aqh[kk][2], aqh[kk][3],
                 sbase + rowoff + kk*32);
            ldm4(aql[kk][0], aql[kk][1], aql[kk][2], aql[kk][3],
                 sbase + AQ_BYTES + rowoff + kk*32);
        }
    }

    float O[8][4];
#pragma unroll
    for (int nt = 0; nt < 8; nt++) {
        O[nt][0] = 0.f; O[nt][1] = 0.f; O[nt][2] = 0.f; O[nt][3] = 0.f;
    }
    float m0 = -1e30f, m1 = -1e30f, l0 = 0.f, l1 = 0.f;

    const int i0 = t0 + 16*warp + g;
    const int i1 = i0 + 8;
    const int njt = qt + 1;               // 128-row macro tiles

    const uint32_t k_rowsel = ((grp >= 2) ? 8 : 0) + rr;
    const uint32_t k_colsel = ((grp & 1) ? 16 : 0);
    const uint32_t v_rowsel = ((grp & 1) ? 8 : 0) + rr;
    const uint32_t v_colsel = ((grp >= 2) ? 16 : 0);

    for (int jt = 0; jt < njt; jt++) {
        const int st = jt & 1;
        if (jt + 1 < njt)
            attn_cp_kv(sbase, st ^ 1, qkvh, qkvl,
                       (size_t)(b_*NT + (jt+1)*128) * 3072 + h*HD, tid);
        if (jt + 1 < njt) cp_wait1(); else cp_wait0();
        __syncthreads();

        const uint32_t sStage = sbase + AKV_OFF + st*AKV_STAGE;
        const bool need_mask = (jt == qt);

#pragma unroll
        for (int sub = 0; sub < 2; sub++) {
            const uint32_t soff = sub * 64 * AROW;
            const uint32_t sKh = sStage + soff;
            const uint32_t sKl = sStage + AKV_BUF + soff;
            const uint32_t sVh = sStage + 2*AKV_BUF + soff;
            const uint32_t sVl = sStage + 3*AKV_BUF + soff;

            float S[8][4];
#pragma unroll
            for (int nt = 0; nt < 8; nt++) {
                S[nt][0] = 0.f; S[nt][1] = 0.f; S[nt][2] = 0.f; S[nt][3] = 0.f;
            }
#pragma unroll
            for (int kk = 0; kk < 4; kk++) {
#pragma unroll
                for (int np = 0; np < 4; np++) {
                    uint32_t addr = (np*16 + k_rowsel)*AROW + kk*32 + k_colsel;
                    uint32_t bh0, bh1, bh2, bh3, bl0, bl1, bl2, bl3;
                    ldm4(bh0, bh1, bh2, bh3, sKh + addr);
                    ldm4(bl0, bl1, bl2, bl3, sKl + addr);
                    mma_bf16(S[2*np],   aqh[kk][0], aqh[kk][1], aqh[kk][2], aqh[kk][3], bh0, bh1);
                    mma_bf16(S[2*np],   aqh[kk][0], aqh[kk][1], aqh[kk][2], aqh[kk][3], bl0, bl1);
                    mma_bf16(S[2*np],   aql[kk][0], aql[kk][1], aql[kk][2], aql[kk][3], bh0, bh1);
                    mma_bf16(S[2*np+1], aqh[kk][0], aqh[kk][1], aqh[kk][2], aqh[kk][3], bh2, bh3);
                    mma_bf16(S[2*np+1], aqh[kk][0], aqh[kk][1], aqh[kk][2], aqh[kk][3], bl2, bl3);
                    mma_bf16(S[2*np+1], aql[kk][0], aql[kk][1], aql[kk][2], aql[kk][3], bh2, bh3);
                }
            }

            const int jbase = jt*128 + sub*64;
#pragma unroll
            for (int nt = 0; nt < 8; nt++) {
                int jb = jbase + nt*8 + qr*2;
                float s0 = S[nt][0] * 8.f, s1 = S[nt][1] * 8.f;
                float s2 = S[nt][2] * 8.f, s3 = S[nt][3] * 8.f;
                if (need_mask) {
                    if (jb     > i0) s0 = -1e30f;
                    if (jb + 1 > i0) s1 = -1e30f;
                    if (jb     > i1) s2 = -1e30f;
                    if (jb + 1 > i1) s3 = -1e30f;
                }
                S[nt][0] = s0; S[nt][1] = s1; S[nt][2] = s2; S[nt][3] = s3;
            }

            float mx0 = -1e30f, mx1 = -1e30f;
#pragma unroll
            for (int nt = 0; nt < 8; nt++) {
                mx0 = fmaxf(mx0, fmaxf(S[nt][0], S[nt][1]));
                mx1 = fmaxf(mx1, fmaxf(S[nt][2], S[nt][3]));
            }
            mx0 = fmaxf(mx0, __shfl_xor_sync(0xffffffffu, mx0, 1));
            mx0 = fmaxf(mx0, __shfl_xor_sync(0xffffffffu, mx0, 2));
            mx1 = fmaxf(mx1, __shfl_xor_sync(0xffffffffu, mx1, 1));
            mx1 = fmaxf(mx1, __shfl_xor_sync(0xffffffffu, mx1, 2));

            float mn0 = fmaxf(m0, mx0), mn1 = fmaxf(m1, mx1);
            float corr0 = __expf(m0 - mn0), corr1 = __expf(m1 - mn1);
            m0 = mn0; m1 = mn1;

            float sum0 = 0.f, sum1 = 0.f;
#pragma unroll
            for (int nt = 0; nt < 8; nt++) {
                float p0 = __expf(S[nt][0] - mn0);
                float p1 = __expf(S[nt][1] - mn0);
                float p2 = __expf(S[nt][2] - mn1);
                float p3 = __expf(S[nt][3] - mn1);
                sum0 += p0 + p1; sum1 += p2 + p3;
                S[nt][0] = p0; S[nt][1] = p1; S[nt][2] = p2; S[nt][3] = p3;
            }
            sum0 += __shfl_xor_sync(0xffffffffu, sum0, 1);
            sum0 += __shfl_xor_sync(0xffffffffu, sum0, 2);
            sum1 += __shfl_xor_sync(0xffffffffu, sum1, 1);
            sum1 += __shfl_xor_sync(0xffffffffu, sum1, 2);
            l0 = l0 * corr0 + sum0;
            l1 = l1 * corr1 + sum1;

#pragma unroll
            for (int nt = 0; nt < 8; nt++) {
                O[nt][0] *= corr0; O[nt][1] *= corr0;
                O[nt][2] *= corr1; O[nt][3] *= corr1;
            }

#pragma unroll
            for (int kk = 0; kk < 4; kk++) {
                uint32_t ah0, ah1, ah2, ah3, al0, al1, al2, al3;
                pack_hilo(S[2*kk][0],   S[2*kk][1],   ah0, al0);
                pack_hilo(S[2*kk][2],   S[2*kk][3],   ah1, al1);
                pack_hilo(S[2*kk+1][0], S[2*kk+1][1], ah2, al2);
                pack_hilo(S[2*kk+1][2], S[2*kk+1][3], ah3, al3);
#pragma unroll
                for (int np = 0; np < 4; np++) {
                    uint32_t addr = (kk*16 + v_rowsel)*AROW + np*32 + v_colsel;
                    uint32_t bh0, bh1, bh2, bh3, bl0, bl1, bl2, bl3;
                    ldm4t(bh0, bh1, bh2, bh3, sVh + addr);
                    ldm4t(bl0, bl1, bl2, bl3, sVl + addr);
                    mma_bf16(O[2*np],   ah0, ah1, ah2, ah3, bh0, bh1);
                    mma_bf16(O[2*np],   ah0, ah1, ah2, ah3, bl0, bl1);
                    mma_bf16(O[2*np],   al0, al1, al2, al3, bh0, bh1);
                    mma_bf16(O[2*np+1], ah0, ah1, ah2, ah3, bh2, bh3);
                    mma_bf16(O[2*np+1], ah0, ah1, ah2, ah3, bl2, bl3);
                    mma_bf16(O[2*np+1], al0, al1, al2, al3, bh2, bh3);
                }
            }
        }
        __syncthreads();
    }

    float inv0 = 1.f / l0, inv1 = 1.f / l1;
    size_t r0 = (size_t)(b_*NT + i0) * NC + h*HD + qr*2;
    size_t r1 = (size_t)(b_*NT + i1) * NC + h*HD + qr*2;
#pragma unroll
    for (int nt = 0; nt < 8; nt++) {
        split_store2(O[nt][0]*inv0, O[nt][1]*inv0, atth + r0 + nt*8, attl + r0 + nt*8);
        split_store2(O[nt][2]*inv1, O[nt][3]*inv1, atth + r1 + nt*8, attl + r1 + nt*8);
    }
}

// ---------------------------------------------------------------------------

extern "C" void kernel_launch(void* const* d_in, const int* in_sizes, int n_in,
                              void* d_out, int out_size)
{
    const float* x      = (const float*)d_in[0];
    const float* W_attn = (const float*)d_in[1];
    const float* W_proj = (const float*)d_in[2];
    const float* b_proj = (const float*)d_in[3];
    float* out = (float*)d_out;

    __nv_bfloat16 *xh, *xl, *wah, *wal, *wph, *wpl, *qkvh, *qkvl, *atth, *attl;
    cudaGetSymbolAddress((void**)&xh,   g_xh);
    cudaGetSymbolAddress((void**)&xl,   g_xl);
    cudaGetSymbolAddress((void**)&wah,  g_wah);
    cudaGetSymbolAddress((void**)&wal,  g_wal);
    cudaGetSymbolAddress((void**)&wph,  g_wph);
    cudaGetSymbolAddress((void**)&wpl,  g_wpl);
    cudaGetSymbolAddress((void**)&qkvh, g_qkvh);
    cudaGetSymbolAddress((void**)&qkvl, g_qkvl);
    cudaGetSymbolAddress((void**)&atth, g_atth);
    cudaGetSymbolAddress((void**)&attl, g_attl);

    cudaFuncSetAttribute(gemm_mma_kernel,
                         cudaFuncAttributeMaxDynamicSharedMemorySize, GEMM_SMEM);
    cudaFuncSetAttribute(attn_fa2_kernel,
                         cudaFuncAttributeMaxDynamicSharedMemorySize, ATT_SMEM);

    split_kernel<<<8192, 256>>>((const float4*)x,      xh,  xl,  2097152);
    split_kernel<<<3072, 256>>>((const float4*)W_attn, wah, wal, 786432);
    split_kernel<<<1024, 256>>>((const float4*)W_proj, wph, wpl, 262144);

    // QKV: [8192,1024] x [3072,1024]^T -> bf16 hi/lo
    gemm_mma_kernel<<<dim3(12, 64), 256, GEMM_SMEM>>>(
        xh, xl, wah, wal, qkvh, qkvl, nullptr, nullptr, 3072, 0);

    attn_fa2_kernel<<<dim3(16, 64), 256, ATT_SMEM>>>(qkvh, qkvl, atth, attl);

    // proj: [8192,1024] x [1024,1024]^T + bias -> f32 out
    gemm_mma_kernel<<<dim3(4, 64), 256, GEMM_SMEM>>>(
        atth, attl, wph, wpl, nullptr, nullptr, out, b_proj, 1024, 1);
}